// round 14
// baseline (speedup 1.0000x reference)
#include <cuda_runtime.h>
#include <cuda_fp16.h>
#include <math.h>
#include <stdint.h>

#define L_  2048
#define B_  8
#define E_  1024
#define Z_  128
#define H_  2048
#define MB_ (L_*B_)   // 16384 rows
#define CH_ 32        // ema chunks
#define CL_ (L_/CH_)  // 64 steps per chunk

// ---------------- scratch (static device allocations; no cudaMalloc) ----------
__device__ __half g_xh  [MB_*E_];
__device__ __half g_emah[MB_*E_];
__device__ float  g_mx  [MB_*Z_];
__device__ __half g_mxh [MB_*Z_];
__device__ __half g_qrh [MB_*Z_];
__device__ __half g_krh [MB_*Z_];
__device__ float  g_u   [MB_*E_];
__device__ __half g_rh  [MB_*H_];
__device__ __half g_vh  [MB_*H_];
__device__ __half g_vTh [(size_t)B_*H_*L_];
__device__ __half g_Sh  [(size_t)B_*L_*L_];
__device__ __half g_hrh [MB_*H_];
__device__ float  g_hend[2*CH_*B_*E_];
__device__ float  g_cin [2*CH_*B_*E_];
// half weights
__device__ __half g_Wph [(E_+2*H_)*E_];
__device__ __half g_Wmh [Z_*E_];
__device__ __half g_Whwh[E_*H_];
__device__ __half g_Whuh[E_*Z_];

__device__ __forceinline__ float sigf (float v){ return 1.f/(1.f+expf(-v)); }
__device__ __forceinline__ float siluf(float v){ return v/(1.f+expf(-v)); }

// ---------------- async / mma helpers -----------------------------------------
#define CP_A16(dst_u32, src_ptr) \
    asm volatile("cp.async.ca.shared.global [%0], [%1], 16;\n" :: "r"(dst_u32), "l"(src_ptr) : "memory")
#define CP_COMMIT() asm volatile("cp.async.commit_group;\n" ::: "memory")
#define CP_WAIT(N)  asm volatile("cp.async.wait_group %0;\n" :: "n"(N) : "memory")

__device__ __forceinline__ void ldsm4(uint32_t (&r)[4], uint32_t addr) {
    asm volatile("ldmatrix.sync.aligned.m8n8.x4.shared.b16 {%0,%1,%2,%3}, [%4];"
        : "=r"(r[0]), "=r"(r[1]), "=r"(r[2]), "=r"(r[3]) : "r"(addr));
}
__device__ __forceinline__ void mma16(float (&c)[4], const uint32_t (&a)[4],
                                      uint32_t b0, uint32_t b1) {
    asm volatile(
        "mma.sync.aligned.m16n8k16.row.col.f32.f16.f16.f32 "
        "{%0,%1,%2,%3},{%4,%5,%6,%7},{%8,%9},{%0,%1,%2,%3};\n"
        : "+f"(c[0]), "+f"(c[1]), "+f"(c[2]), "+f"(c[3])
        : "r"(a[0]), "r"(a[1]), "r"(a[2]), "r"(a[3]), "r"(b0), "r"(b1));
}

// ---------------- fp16 NT gemm core --------------------------------------------
// block tile 128x128, 256 threads, 8 warps (2x4), warp tile 64x32,
// BK=64 halves, 3-stage cp.async ring (wait_group 1). 16 warps/SM (2 CTAs).

struct StageH { __half A[128][72]; __half B[128][72]; };   // 144B row pitch
#define NSTG 3
#define SMEM_BYTES (NSTG*(int)sizeof(StageH))

// load 128 rows x 64 halves (128B) tile; 1024 16B-chunks, 256 threads -> 4 each
__device__ __forceinline__ void cpa_h(__half (*t)[72], const __half* __restrict__ src,
                                      int ld, int r0, int k0, int tid) {
    #pragma unroll
    for (int it = 0; it < 4; it++) {
        int i = tid + 256*it;
        int row = i >> 3, c = i & 7;
        uint32_t dst = (uint32_t)__cvta_generic_to_shared(&t[row][c*8]);
        CP_A16(dst, src + (size_t)(r0+row)*ld + k0 + c*8);
    }
}

// C += A(M,K) * B(N,K)^T ; K multiple of 64, K/64 >= 2
__device__ __forceinline__ void gemm_nt_h(const __half* __restrict__ A, int lda,
                                          const __half* __restrict__ B, int ldb,
                                          int K, int m0, int n0,
                                          StageH* st, float (&acc)[4][4][4]) {
    const int tid = threadIdx.x;
    const int wid = tid >> 5, lane = tid & 31;
    const int wm = (wid >> 2) * 64, wn = (wid & 3) * 32;
    const int nk = K >> 6;
    #pragma unroll
    for (int s = 0; s < 2; s++) {
        cpa_h(st[s].A, A, lda, m0, s<<6, tid);
        cpa_h(st[s].B, B, ldb, n0, s<<6, tid);
        CP_COMMIT();
    }
    for (int i = 0; i < nk; i++) {
        CP_WAIT(1);               // stage i's group complete; i+1 may be in flight
        __syncthreads();          // stage i visible; all warps past mma(i-1)
        if (i + 2 < nk) {
            StageH& pb = st[(i+2) % 3];
            cpa_h(pb.A, A, lda, m0, (i+2)<<6, tid);
            cpa_h(pb.B, B, ldb, n0, (i+2)<<6, tid);
        }
        CP_COMMIT();              // exactly one group per iteration
        StageH& s = st[i % 3];
        uint32_t abase = (uint32_t)__cvta_generic_to_shared(&s.A[wm + (lane & 15)][(lane >> 4) * 8]);
        uint32_t bbase = (uint32_t)__cvta_generic_to_shared(&s.B[wn + (lane & 15)][(lane >> 4) * 8]);
        #pragma unroll
        for (int kk = 0; kk < 4; kk++) {            // four k16 sub-steps (32B each)
            uint32_t a[4][4], bf[2][4];
            #pragma unroll
            for (int mt = 0; mt < 4; mt++) ldsm4(a[mt],  abase + mt*16*144 + kk*32);
            #pragma unroll
            for (int np = 0; np < 2; np++) ldsm4(bf[np], bbase + np*16*144 + kk*32);
            #pragma unroll
            for (int nt = 0; nt < 4; nt++) {
                uint32_t b0 = bf[nt >> 1][nt & 1];
                uint32_t b1 = bf[nt >> 1][2 + (nt & 1)];
                #pragma unroll
                for (int mt = 0; mt < 4; mt++) mma16(acc[mt][nt], a[mt], b0, b1);
            }
        }
    }
    __syncthreads();              // protect ring reuse by a following gemm call
}

#define ZERO_ACC4(acc) { _Pragma("unroll") for (int i=0;i<4;i++) _Pragma("unroll") for (int j=0;j<4;j++) _Pragma("unroll") for (int q=0;q<4;q++) acc[i][j][q]=0.f; }

// epilogue pairs: (row, col) with v0, v1 at columns col, col+1 (col even)
#define EPI2_BEGIN \
    { const int wid_ = threadIdx.x >> 5, lane_ = threadIdx.x & 31; \
      const int wm_ = (wid_ >> 2)*64, wn_ = (wid_ & 3)*32; \
      const int g_ = lane_ >> 2, t_ = lane_ & 3; \
      _Pragma("unroll") for (int mt = 0; mt < 4; mt++) \
      _Pragma("unroll") for (int nt = 0; nt < 4; nt++) \
      _Pragma("unroll") for (int hq = 0; hq < 2; hq++) { \
          int row = m0 + wm_ + mt*16 + g_ + 8*hq; \
          int col = n0 + wn_ + nt*8 + 2*t_; \
          float v0 = acc[mt][nt][2*hq], v1 = acc[mt][nt][2*hq+1];
#define EPI2_END } }

// ---------------- fp32 -> fp16 conversion --------------------------------------
__global__ void __launch_bounds__(256) k_cvt(const float* __restrict__ s,
                                             __half* __restrict__ d) {
    int i = (blockIdx.x*256 + threadIdx.x) * 4;
    float4 f = *(const float4*)(s + i);
    *(__half2*)(d + i)     = __floats2half2_rn(f.x, f.y);
    *(__half2*)(d + i + 2) = __floats2half2_rn(f.z, f.w);
}

// ---------------- EMA: 3-phase chunked linear scan -----------------------------
__device__ __forceinline__ void ema_params(int e, const float* delta, const float* alpha,
        float& q0, float& q1) {
    float p0 = sigf(delta[e*2+0]);
    float p1 = sigf(delta[e*2+1]);
    q0 = 1.f - p0*sigf(alpha[e*2+0]);
    q1 = 1.f - p1*sigf(alpha[e*2+1]);
}

__global__ void __launch_bounds__(256) k_ema_a(const float* __restrict__ x,
        const float* __restrict__ delta, const float* __restrict__ alpha)
{
    const int gt = blockIdx.x*256 + threadIdx.x;
    const int be = gt & (B_*E_-1);
    const int c  = gt >> 13;
    const int e  = be & (E_-1);
    float q0, q1; ema_params(e, delta, alpha, q0, q1);
    float h0 = 0.f, h1 = 0.f;
    const float* xp = x + (size_t)(c*CL_)*(B_*E_) + be;
    #pragma unroll 4
    for (int l = 0; l < CL_; l++) {
        float xv = xp[(size_t)l*(B_*E_)];
        h0 = q0*h0 + xv;
        h1 = q1*h1 + xv;
    }
    g_hend[(size_t)c*(B_*E_) + be]       = h0;
    g_hend[(size_t)(CH_+c)*(B_*E_) + be] = h1;
}

__global__ void __launch_bounds__(256) k_ema_b(const float* __restrict__ delta,
        const float* __restrict__ alpha)
{
    const int be = blockIdx.x*256 + threadIdx.x;
    const int e  = be & (E_-1);
    float q0, q1; ema_params(e, delta, alpha, q0, q1);
    float qp0 = q0, qp1 = q1;
    #pragma unroll
    for (int i = 0; i < 6; i++) { qp0 *= qp0; qp1 *= qp1; }   // q^64
    float c0 = 0.f, c1 = 0.f;
    for (int c = 0; c < CH_; c++) {
        g_cin[(size_t)c*(B_*E_) + be]       = c0;
        g_cin[(size_t)(CH_+c)*(B_*E_) + be] = c1;
        c0 = qp0*c0 + g_hend[(size_t)c*(B_*E_) + be];
        c1 = qp1*c1 + g_hend[(size_t)(CH_+c)*(B_*E_) + be];
    }
}

__global__ void __launch_bounds__(256) k_ema_c(const float* __restrict__ x,
        const float* __restrict__ delta, const float* __restrict__ alpha,
        const float* __restrict__ ebeta, const float* __restrict__ egam,
        const float* __restrict__ omega)
{
    const int gt = blockIdx.x*256 + threadIdx.x;
    const int be = gt & (B_*E_-1);
    const int c  = gt >> 13;
    const int e  = be & (E_-1);
    float p0 = sigf(delta[e*2+0]);
    float p1 = sigf(delta[e*2+1]);
    float q0 = 1.f - p0*sigf(alpha[e*2+0]);
    float q1 = 1.f - p1*sigf(alpha[e*2+1]);
    const float sc = 0.70710678118654752f;
    float c0 = p0*ebeta[e*2+0]*egam[e*2+0]*sc;
    float c1 = p1*ebeta[e*2+1]*egam[e*2+1]*sc;
    float om = omega[e];
    float h0 = g_cin[(size_t)c*(B_*E_) + be];
    float h1 = g_cin[(size_t)(CH_+c)*(B_*E_) + be];
    const size_t base = (size_t)(c*CL_)*(B_*E_) + be;
    #pragma unroll 4
    for (int l = 0; l < CL_; l++) {
        float xv = x[base + (size_t)l*(B_*E_)];
        h0 = q0*h0 + xv;
        h1 = q1*h1 + xv;
        float o = c0*h0 + c1*h1 + xv*om;
        g_emah[base + (size_t)l*(B_*E_)] = __float2half_rn(siluf(o));
    }
}

// ---------------- kernel 2: mx = ema @ Wm^T + bm (fp32 + half outputs) ----------
__global__ void __launch_bounds__(256, 2) k_mx(const float* __restrict__ bm)
{
    extern __shared__ StageH st_dyn[];
    float acc[4][4][4]; ZERO_ACC4(acc);
    const int m0 = blockIdx.y*128, n0 = blockIdx.x*128;
    gemm_nt_h(g_emah, E_, g_Wmh, E_, E_, m0, n0, st_dyn, acc);
    EPI2_BEGIN
        float o0 = v0 + bm[col], o1 = v1 + bm[col+1];
        *(float2*)&g_mx[(size_t)row*Z_ + col] = make_float2(o0, o1);
        *(__half2*)&g_mxh[(size_t)row*Z_ + col] = __floats2half2_rn(o0, o1);
    EPI2_END
}

// ---------------- kernel 3: z (fp32 FFMA for precision; tiny) -------------------
struct TilesF { float As[16][132]; float Bs[16][132]; };
__global__ void __launch_bounds__(256) k_z(const float* __restrict__ Wz,
        const float* __restrict__ bz, const float* __restrict__ gamma,
        const float* __restrict__ beta)
{
    __shared__ TilesF s;
    float acc[8][8];
    #pragma unroll
    for (int i=0;i<8;i++)
        #pragma unroll
        for (int j=0;j<8;j++) acc[i][j]=0.f;
    const int m0 = blockIdx.y*128;
    const int tid = threadIdx.x;
    const int tm = (tid >> 4) << 3, tn = (tid & 15) << 3;
    for (int k0 = 0; k0 < Z_; k0 += 16) {
        #pragma unroll
        for (int j = 0; j < 8; j++) {
            int i = tid + 256*j;
            int row = i >> 4, kk = i & 15;
            s.As[kk][row] = g_mx[(size_t)(m0+row)*Z_ + k0 + kk];
            s.Bs[kk][row] = Wz[(size_t)row*Z_ + k0 + kk];
        }
        __syncthreads();
        #pragma unroll
        for (int kk = 0; kk < 16; kk++) {
            float a[8], b[8];
            *(float4*)&a[0] = *(const float4*)&s.As[kk][tm];
            *(float4*)&a[4] = *(const float4*)&s.As[kk][tm+4];
            *(float4*)&b[0] = *(const float4*)&s.Bs[kk][tn];
            *(float4*)&b[4] = *(const float4*)&s.Bs[kk][tn+4];
            #pragma unroll
            for (int i = 0; i < 8; i++)
                #pragma unroll
                for (int j = 0; j < 8; j++)
                    acc[i][j] += a[i]*b[j];
        }
        __syncthreads();
    }
    #pragma unroll
    for (int i = 0; i < 8; i++)
        #pragma unroll
        for (int j = 0; j < 8; j++) {
            int m = m0+tm+i, n = tn+j;
            float zz = siluf(acc[i][j] + bz[n]);
            g_qrh[(size_t)m*Z_ + n] = __float2half_rn(zz*gamma[n]    + beta[n]);
            g_krh[(size_t)m*Z_ + n] = __float2half_rn(zz*gamma[Z_+n] + beta[Z_+n]);
        }
}

// ---------------- kernel 4: base = x @ Wp^T + bp -> u(fp32), r(half), v(half) ---
__global__ void __launch_bounds__(256, 2) k_base(const float* __restrict__ bp)
{
    extern __shared__ StageH st_dyn[];
    float acc[4][4][4]; ZERO_ACC4(acc);
    const int m0 = blockIdx.y*128, n0 = blockIdx.x*128;
    gemm_nt_h(g_xh, E_, g_Wph, E_, E_, m0, n0, st_dyn, acc);
    EPI2_BEGIN
        float t0 = v0 + bp[col], t1 = v1 + bp[col+1];
        if (col < E_) {
            *(float2*)&g_u[(size_t)row*E_ + col] = make_float2(sigf(t0), sigf(t1));
        } else {
            float s0 = siluf(t0), s1 = siluf(t1);
            int n2 = col - E_;
            if (n2 < H_) *(__half2*)&g_rh[(size_t)row*H_ + n2]      = __floats2half2_rn(s0, s1);
            else         *(__half2*)&g_vh[(size_t)row*H_ + (n2-H_)] = __floats2half2_rn(s0, s1);
        }
    EPI2_END
}

// ---------------- kernel 4b: vT[b][h][l] = v[(l*B+b)][h] ------------------------
__global__ void __launch_bounds__(256) k_vT()
{
    __shared__ __half t[32][33];
    const int b  = blockIdx.z;
    const int h0 = blockIdx.x*32, l0 = blockIdx.y*32;
    const int tx = threadIdx.x & 31, ty = threadIdx.x >> 5;   // 32x8
    #pragma unroll
    for (int i = 0; i < 4; i++) {
        int l = l0 + ty + 8*i;
        t[ty + 8*i][tx] = g_vh[((size_t)l*B_ + b)*H_ + h0 + tx];
    }
    __syncthreads();
    #pragma unroll
    for (int i = 0; i < 4; i++) {
        int h = h0 + ty + 8*i;
        g_vTh[(size_t)b*H_*L_ + (size_t)h*L_ + l0 + tx] = t[tx][ty + 8*i];
    }
}

// ---------------- kernel 5: S = relu(q k^T / L + bias)^2, causal, half out ------
__global__ void __launch_bounds__(256, 2) k_S(const float* __restrict__ rpw)
{
    const int b  = blockIdx.z;
    const int m0 = blockIdx.y*128, n0 = blockIdx.x*128;
    if (n0 > m0) return;
    extern __shared__ StageH st_dyn[];
    float acc[4][4][4]; ZERO_ACC4(acc);
    gemm_nt_h(g_qrh + b*Z_, B_*Z_, g_krh + b*Z_, B_*Z_, Z_, m0, n0, st_dyn, acc);
    __half* Sb = g_Sh + (size_t)b*L_*L_;
    const float inv = 1.f / (float)L_;
    EPI2_BEGIN
        float a0 = v0*inv + rpw[(L_-1) + col   - row];
        float a1 = v1*inv + rpw[(L_-1) + col+1 - row];
        a0 = (col   <= row) ? fmaxf(a0, 0.f) : 0.f;
        a1 = (col+1 <= row) ? fmaxf(a1, 0.f) : 0.f;
        *(__half2*)&Sb[(size_t)row*L_ + col] = __floats2half2_rn(a0*a0, a1*a1);
    EPI2_END
}

// ---------------- kernel 6: hr = (S @ v) * r  (NT with vT, causal K trunc) ------
__global__ void __launch_bounds__(256, 2) k_h()
{
    const int b  = blockIdx.z;
    const int m0 = blockIdx.y*128, n0 = blockIdx.x*128;
    extern __shared__ StageH st_dyn[];
    float acc[4][4][4]; ZERO_ACC4(acc);
    gemm_nt_h(g_Sh + (size_t)b*L_*L_, L_,
              g_vTh + (size_t)b*H_*L_, L_,
              m0 + 128, m0, n0, st_dyn, acc);
    EPI2_BEGIN
        size_t idx = (size_t)(row*B_ + b)*H_ + col;
        __half2 rr = *(const __half2*)&g_rh[idx];
        float2 rf = __half22float2(rr);
        *(__half2*)&g_hrh[idx] = __floats2half2_rn(v0*rf.x, v1*rf.y);
    EPI2_END
}

// ---------------- kernel 7: out = x + u*(tanh(hr Whw^T + mx Whu^T + b) - x) -----
__global__ void __launch_bounds__(256, 2) k_final(const float* __restrict__ x,
        const float* __restrict__ bhw, const float* __restrict__ bhu,
        float* __restrict__ out)
{
    extern __shared__ StageH st_dyn[];
    float acc[4][4][4]; ZERO_ACC4(acc);
    const int m0 = blockIdx.y*128, n0 = blockIdx.x*128;
    gemm_nt_h(g_hrh, H_, g_Whwh, H_, H_, m0, n0, st_dyn, acc);
    gemm_nt_h(g_mxh, Z_, g_Whuh, Z_, Z_, m0, n0, st_dyn, acc);
    EPI2_BEGIN
        float t0 = v0 + bhw[col]   + bhu[col];
        float t1 = v1 + bhw[col+1] + bhu[col+1];
        size_t idx = (size_t)row*E_ + col;
        float2 xv = *(const float2*)&x[idx];
        float2 uu = *(const float2*)&g_u[idx];
        float2 o = make_float2(xv.x + uu.x*(tanhf(t0) - xv.x),
                               xv.y + uu.y*(tanhf(t1) - xv.y));
        *(float2*)&out[idx] = o;
    EPI2_END
}

// -----------------------------------------------------------------------------
extern "C" void kernel_launch(void* const* d_in, const int* in_sizes, int n_in,
                              void* d_out, int out_size)
{
    const float* x     = (const float*)d_in[0];
    const float* delta = (const float*)d_in[2];
    const float* alpha = (const float*)d_in[3];
    const float* ebeta = (const float*)d_in[4];
    const float* egam  = (const float*)d_in[5];
    const float* omega = (const float*)d_in[6];
    const float* Wm    = (const float*)d_in[7];
    const float* bm    = (const float*)d_in[8];
    const float* Wz    = (const float*)d_in[9];
    const float* bz    = (const float*)d_in[10];
    const float* Wp    = (const float*)d_in[11];
    const float* bp    = (const float*)d_in[12];
    const float* Whw   = (const float*)d_in[13];
    const float* bhw   = (const float*)d_in[14];
    const float* Whu   = (const float*)d_in[15];
    const float* bhu   = (const float*)d_in[16];
    const float* gamma = (const float*)d_in[17];
    const float* beta  = (const float*)d_in[18];
    const float* rpw   = (const float*)d_in[19];
    float* out = (float*)d_out;

    __half *xh_p, *Wph_p, *Wmh_p, *Whwh_p, *Whuh_p;
    cudaGetSymbolAddress((void**)&xh_p,   g_xh);
    cudaGetSymbolAddress((void**)&Wph_p,  g_Wph);
    cudaGetSymbolAddress((void**)&Wmh_p,  g_Wmh);
    cudaGetSymbolAddress((void**)&Whwh_p, g_Whwh);
    cudaGetSymbolAddress((void**)&Whuh_p, g_Whuh);

    cudaFuncSetAttribute(k_mx,    cudaFuncAttributeMaxDynamicSharedMemorySize, SMEM_BYTES);
    cudaFuncSetAttribute(k_base,  cudaFuncAttributeMaxDynamicSharedMemorySize, SMEM_BYTES);
    cudaFuncSetAttribute(k_S,     cudaFuncAttributeMaxDynamicSharedMemorySize, SMEM_BYTES);
    cudaFuncSetAttribute(k_h,     cudaFuncAttributeMaxDynamicSharedMemorySize, SMEM_BYTES);
    cudaFuncSetAttribute(k_final, cudaFuncAttributeMaxDynamicSharedMemorySize, SMEM_BYTES);

    static cudaStream_t s2 = nullptr;
    static cudaEvent_t e_fork = nullptr, e_join = nullptr;
    if (s2 == nullptr) {
        cudaStreamCreateWithFlags(&s2, cudaStreamNonBlocking);
        cudaEventCreateWithFlags(&e_fork, cudaEventDisableTiming);
        cudaEventCreateWithFlags(&e_join, cudaEventDisableTiming);
    }

    cudaEventRecord(e_fork, 0);
    cudaStreamWaitEvent(s2, e_fork, 0);

    // ---- branch A on s2: cvt(x, Wp) -> k_base -> k_vT ----
    k_cvt <<<MB_*E_/1024, 256, 0, s2>>>(x,  xh_p);
    k_cvt <<<(E_+2*H_)*E_/1024, 256, 0, s2>>>(Wp, Wph_p);
    k_base<<<dim3(40, 128), 256, SMEM_BYTES, s2>>>(bp);
    k_vT  <<<dim3(H_/32, L_/32, B_), 256, 0, s2>>>();
    cudaEventRecord(e_join, s2);

    // ---- branch B on default stream ----
    k_cvt  <<<Z_*E_/1024, 256>>>(Wm,  Wmh_p);
    k_cvt  <<<E_*H_/1024, 256>>>(Whw, Whwh_p);
    k_cvt  <<<E_*Z_/1024, 256>>>(Whu, Whuh_p);
    k_ema_a<<<CH_*B_*E_/256, 256>>>(x, delta, alpha);
    k_ema_b<<<B_*E_/256, 256>>>(delta, alpha);
    k_ema_c<<<CH_*B_*E_/256, 256>>>(x, delta, alpha, ebeta, egam, omega);
    k_mx   <<<dim3(1, 128),    256, SMEM_BYTES>>>(bm);
    k_z    <<<dim3(1, 128),    256>>>(Wz, bz, gamma, beta);
    k_S    <<<dim3(16, 16, 8), 256, SMEM_BYTES>>>(rpw);

    // ---- join: k_h needs S (B) + vT, r (A) ----
    cudaStreamWaitEvent(0, e_join, 0);
    k_h    <<<dim3(16, 16, 8), 256, SMEM_BYTES>>>();
    k_final<<<dim3(8, 128),    256, SMEM_BYTES>>>(x, bhw, bhu, out);
}

// round 15
// speedup vs baseline: 1.1429x; 1.1429x over previous
#include <cuda_runtime.h>
#include <cuda_fp16.h>
#include <math.h>
#include <stdint.h>

#define L_  2048
#define B_  8
#define E_  1024
#define Z_  128
#define H_  2048
#define MB_ (L_*B_)   // 16384 rows
#define CH_ 32        // ema chunks
#define CL_ (L_/CH_)  // 64 steps per chunk

// ---------------- scratch (static device allocations; no cudaMalloc) ----------
__device__ __half g_xh  [MB_*E_];
__device__ __half g_emah[MB_*E_];
__device__ float  g_mx  [MB_*Z_];
__device__ __half g_mxh [MB_*Z_];
__device__ __half g_qrh [MB_*Z_];
__device__ __half g_krh [MB_*Z_];
__device__ float  g_u   [MB_*E_];
__device__ __half g_rh  [MB_*H_];
__device__ __half g_vh  [MB_*H_];
__device__ __half g_vTh [(size_t)B_*H_*L_];
__device__ __half g_Sh  [(size_t)B_*L_*L_];
__device__ __half g_hrh [MB_*H_];
__device__ float  g_hend[2*CH_*B_*E_];
__device__ float  g_cin [2*CH_*B_*E_];
// half weights
__device__ __half g_Wph [(E_+2*H_)*E_];
__device__ __half g_Wmh [Z_*E_];
__device__ __half g_Whwh[E_*H_];
__device__ __half g_Whuh[E_*Z_];

__device__ __forceinline__ float sigf (float v){ return 1.f/(1.f+expf(-v)); }
__device__ __forceinline__ float siluf(float v){ return v/(1.f+expf(-v)); }

// ---------------- async / mma helpers -----------------------------------------
#define CP_A16(dst_u32, src_ptr) \
    asm volatile("cp.async.ca.shared.global [%0], [%1], 16;\n" :: "r"(dst_u32), "l"(src_ptr) : "memory")
#define CP_COMMIT() asm volatile("cp.async.commit_group;\n" ::: "memory")
#define CP_WAIT(N)  asm volatile("cp.async.wait_group %0;\n" :: "n"(N) : "memory")

__device__ __forceinline__ void ldsm4(uint32_t (&r)[4], uint32_t addr) {
    asm volatile("ldmatrix.sync.aligned.m8n8.x4.shared.b16 {%0,%1,%2,%3}, [%4];"
        : "=r"(r[0]), "=r"(r[1]), "=r"(r[2]), "=r"(r[3]) : "r"(addr));
}
__device__ __forceinline__ void mma16(float (&c)[4], const uint32_t (&a)[4],
                                      uint32_t b0, uint32_t b1) {
    asm volatile(
        "mma.sync.aligned.m16n8k16.row.col.f32.f16.f16.f32 "
        "{%0,%1,%2,%3},{%4,%5,%6,%7},{%8,%9},{%0,%1,%2,%3};\n"
        : "+f"(c[0]), "+f"(c[1]), "+f"(c[2]), "+f"(c[3])
        : "r"(a[0]), "r"(a[1]), "r"(a[2]), "r"(a[3]), "r"(b0), "r"(b1));
}

// ---------------- fp16 NT gemm core --------------------------------------------
// block tile 128x128, 256 threads, 8 warps (2x4), warp tile 64x32,
// BK=64 halves, XOR-swizzled 128B-pitch smem (no padding),
// 3-stage cp.async ring (wait_group 1). 96KB/CTA -> 2 CTAs/SM, 16 warps/SM.

struct StageH { __half A[128*64]; __half B[128*64]; };   // 32KB, 128B rows, swizzled
#define NSTG 3
#define SMEM_BYTES (NSTG*(int)sizeof(StageH))

// swizzled store: chunk (16B) index within row XORed with (row&7)
__device__ __forceinline__ void cpa_h(__half* t, const __half* __restrict__ src,
                                      int ld, int r0, int k0, int tid) {
    #pragma unroll
    for (int it = 0; it < 4; it++) {
        int i = tid + 256*it;
        int row = i >> 3, c = i & 7;
        uint32_t off = (uint32_t)row*128u + (((uint32_t)c*16u) ^ (((uint32_t)row & 7u)*16u));
        uint32_t dst = (uint32_t)__cvta_generic_to_shared((char*)t + off);
        CP_A16(dst, src + (size_t)(r0+row)*ld + k0 + c*8);
    }
}

// C += A(M,K) * B(N,K)^T ; K multiple of 64, K/64 >= 2
__device__ __forceinline__ void gemm_nt_h(const __half* __restrict__ A, int lda,
                                          const __half* __restrict__ B, int ldb,
                                          int K, int m0, int n0,
                                          StageH* st, float (&acc)[4][4][4]) {
    const int tid = threadIdx.x;
    const int wid = tid >> 5, lane = tid & 31;
    const int wm = (wid >> 2) * 64, wn = (wid & 3) * 32;
    const int nk = K >> 6;
    const uint32_t xorv = (uint32_t)(lane & 7) * 16u;
    const uint32_t cb0  = (uint32_t)(lane >> 4) * 16u;
    #pragma unroll
    for (int s = 0; s < 2; s++) {
        cpa_h(st[s].A, A, lda, m0, s<<6, tid);
        cpa_h(st[s].B, B, ldb, n0, s<<6, tid);
        CP_COMMIT();
    }
    for (int i = 0; i < nk; i++) {
        CP_WAIT(1);               // stage i's group complete; i+1 may be in flight
        __syncthreads();          // stage i visible; all warps past mma(i-1)
        if (i + 2 < nk) {
            StageH& pb = st[(i+2) % 3];
            cpa_h(pb.A, A, lda, m0, (i+2)<<6, tid);
            cpa_h(pb.B, B, ldb, n0, (i+2)<<6, tid);
        }
        CP_COMMIT();              // exactly one group per iteration
        StageH& s = st[i % 3];
        uint32_t abase = (uint32_t)__cvta_generic_to_shared(s.A) + (uint32_t)(wm + (lane & 15))*128u;
        uint32_t bbase = (uint32_t)__cvta_generic_to_shared(s.B) + (uint32_t)(wn + (lane & 15))*128u;
        #pragma unroll
        for (int kk = 0; kk < 4; kk++) {            // four k16 sub-steps (32B each)
            uint32_t cb = (cb0 | ((uint32_t)kk*32u)) ^ xorv;
            uint32_t a[4][4], bf[2][4];
            #pragma unroll
            for (int mt = 0; mt < 4; mt++) ldsm4(a[mt],  abase + (uint32_t)mt*2048u + cb);
            #pragma unroll
            for (int np = 0; np < 2; np++) ldsm4(bf[np], bbase + (uint32_t)np*2048u + cb);
            #pragma unroll
            for (int nt = 0; nt < 4; nt++) {
                uint32_t b0 = bf[nt >> 1][nt & 1];
                uint32_t b1 = bf[nt >> 1][2 + (nt & 1)];
                #pragma unroll
                for (int mt = 0; mt < 4; mt++) mma16(acc[mt][nt], a[mt], b0, b1);
            }
        }
    }
    __syncthreads();              // protect ring reuse by a following gemm call
}

#define ZERO_ACC4(acc) { _Pragma("unroll") for (int i=0;i<4;i++) _Pragma("unroll") for (int j=0;j<4;j++) _Pragma("unroll") for (int q=0;q<4;q++) acc[i][j][q]=0.f; }

// epilogue pairs: (row, col) with v0, v1 at columns col, col+1 (col even)
#define EPI2_BEGIN \
    { const int wid_ = threadIdx.x >> 5, lane_ = threadIdx.x & 31; \
      const int wm_ = (wid_ >> 2)*64, wn_ = (wid_ & 3)*32; \
      const int g_ = lane_ >> 2, t_ = lane_ & 3; \
      _Pragma("unroll") for (int mt = 0; mt < 4; mt++) \
      _Pragma("unroll") for (int nt = 0; nt < 4; nt++) \
      _Pragma("unroll") for (int hq = 0; hq < 2; hq++) { \
          int row = m0 + wm_ + mt*16 + g_ + 8*hq; \
          int col = n0 + wn_ + nt*8 + 2*t_; \
          float v0 = acc[mt][nt][2*hq], v1 = acc[mt][nt][2*hq+1];
#define EPI2_END } }

// ---------------- fp32 -> fp16 conversion --------------------------------------
__global__ void __launch_bounds__(256) k_cvt(const float* __restrict__ s,
                                             __half* __restrict__ d) {
    int i = (blockIdx.x*256 + threadIdx.x) * 4;
    float4 f = *(const float4*)(s + i);
    *(__half2*)(d + i)     = __floats2half2_rn(f.x, f.y);
    *(__half2*)(d + i + 2) = __floats2half2_rn(f.z, f.w);
}

// ---------------- EMA: 3-phase chunked linear scan -----------------------------
__device__ __forceinline__ void ema_params(int e, const float* delta, const float* alpha,
        float& q0, float& q1) {
    float p0 = sigf(delta[e*2+0]);
    float p1 = sigf(delta[e*2+1]);
    q0 = 1.f - p0*sigf(alpha[e*2+0]);
    q1 = 1.f - p1*sigf(alpha[e*2+1]);
}

__global__ void __launch_bounds__(256) k_ema_a(const float* __restrict__ x,
        const float* __restrict__ delta, const float* __restrict__ alpha)
{
    const int gt = blockIdx.x*256 + threadIdx.x;
    const int be = gt & (B_*E_-1);
    const int c  = gt >> 13;
    const int e  = be & (E_-1);
    float q0, q1; ema_params(e, delta, alpha, q0, q1);
    float h0 = 0.f, h1 = 0.f;
    const float* xp = x + (size_t)(c*CL_)*(B_*E_) + be;
    #pragma unroll 4
    for (int l = 0; l < CL_; l++) {
        float xv = xp[(size_t)l*(B_*E_)];
        h0 = q0*h0 + xv;
        h1 = q1*h1 + xv;
    }
    g_hend[(size_t)c*(B_*E_) + be]       = h0;
    g_hend[(size_t)(CH_+c)*(B_*E_) + be] = h1;
}

__global__ void __launch_bounds__(256) k_ema_b(const float* __restrict__ delta,
        const float* __restrict__ alpha)
{
    const int be = blockIdx.x*256 + threadIdx.x;
    const int e  = be & (E_-1);
    float q0, q1; ema_params(e, delta, alpha, q0, q1);
    float qp0 = q0, qp1 = q1;
    #pragma unroll
    for (int i = 0; i < 6; i++) { qp0 *= qp0; qp1 *= qp1; }   // q^64
    float c0 = 0.f, c1 = 0.f;
    for (int c = 0; c < CH_; c++) {
        g_cin[(size_t)c*(B_*E_) + be]       = c0;
        g_cin[(size_t)(CH_+c)*(B_*E_) + be] = c1;
        c0 = qp0*c0 + g_hend[(size_t)c*(B_*E_) + be];
        c1 = qp1*c1 + g_hend[(size_t)(CH_+c)*(B_*E_) + be];
    }
}

__global__ void __launch_bounds__(256) k_ema_c(const float* __restrict__ x,
        const float* __restrict__ delta, const float* __restrict__ alpha,
        const float* __restrict__ ebeta, const float* __restrict__ egam,
        const float* __restrict__ omega)
{
    const int gt = blockIdx.x*256 + threadIdx.x;
    const int be = gt & (B_*E_-1);
    const int c  = gt >> 13;
    const int e  = be & (E_-1);
    float p0 = sigf(delta[e*2+0]);
    float p1 = sigf(delta[e*2+1]);
    float q0 = 1.f - p0*sigf(alpha[e*2+0]);
    float q1 = 1.f - p1*sigf(alpha[e*2+1]);
    const float sc = 0.70710678118654752f;
    float c0 = p0*ebeta[e*2+0]*egam[e*2+0]*sc;
    float c1 = p1*ebeta[e*2+1]*egam[e*2+1]*sc;
    float om = omega[e];
    float h0 = g_cin[(size_t)c*(B_*E_) + be];
    float h1 = g_cin[(size_t)(CH_+c)*(B_*E_) + be];
    const size_t base = (size_t)(c*CL_)*(B_*E_) + be;
    #pragma unroll 4
    for (int l = 0; l < CL_; l++) {
        float xv = x[base + (size_t)l*(B_*E_)];
        h0 = q0*h0 + xv;
        h1 = q1*h1 + xv;
        float o = c0*h0 + c1*h1 + xv*om;
        g_emah[base + (size_t)l*(B_*E_)] = __float2half_rn(siluf(o));
    }
}

// ---------------- kernel 2: mx = ema @ Wm^T + bm (fp32 + half outputs) ----------
__global__ void __launch_bounds__(256, 2) k_mx(const float* __restrict__ bm)
{
    extern __shared__ StageH st_dyn[];
    float acc[4][4][4]; ZERO_ACC4(acc);
    const int m0 = blockIdx.y*128, n0 = blockIdx.x*128;
    gemm_nt_h(g_emah, E_, g_Wmh, E_, E_, m0, n0, st_dyn, acc);
    EPI2_BEGIN
        float o0 = v0 + bm[col], o1 = v1 + bm[col+1];
        *(float2*)&g_mx[(size_t)row*Z_ + col] = make_float2(o0, o1);
        *(__half2*)&g_mxh[(size_t)row*Z_ + col] = __floats2half2_rn(o0, o1);
    EPI2_END
}

// ---------------- kernel 3: z (fp32 FFMA for precision; tiny) -------------------
struct TilesF { float As[16][132]; float Bs[16][132]; };
__global__ void __launch_bounds__(256) k_z(const float* __restrict__ Wz,
        const float* __restrict__ bz, const float* __restrict__ gamma,
        const float* __restrict__ beta)
{
    __shared__ TilesF s;
    float acc[8][8];
    #pragma unroll
    for (int i=0;i<8;i++)
        #pragma unroll
        for (int j=0;j<8;j++) acc[i][j]=0.f;
    const int m0 = blockIdx.y*128;
    const int tid = threadIdx.x;
    const int tm = (tid >> 4) << 3, tn = (tid & 15) << 3;
    for (int k0 = 0; k0 < Z_; k0 += 16) {
        #pragma unroll
        for (int j = 0; j < 8; j++) {
            int i = tid + 256*j;
            int row = i >> 4, kk = i & 15;
            s.As[kk][row] = g_mx[(size_t)(m0+row)*Z_ + k0 + kk];
            s.Bs[kk][row] = Wz[(size_t)row*Z_ + k0 + kk];
        }
        __syncthreads();
        #pragma unroll
        for (int kk = 0; kk < 16; kk++) {
            float a[8], b[8];
            *(float4*)&a[0] = *(const float4*)&s.As[kk][tm];
            *(float4*)&a[4] = *(const float4*)&s.As[kk][tm+4];
            *(float4*)&b[0] = *(const float4*)&s.Bs[kk][tn];
            *(float4*)&b[4] = *(const float4*)&s.Bs[kk][tn+4];
            #pragma unroll
            for (int i = 0; i < 8; i++)
                #pragma unroll
                for (int j = 0; j < 8; j++)
                    acc[i][j] += a[i]*b[j];
        }
        __syncthreads();
    }
    #pragma unroll
    for (int i = 0; i < 8; i++)
        #pragma unroll
        for (int j = 0; j < 8; j++) {
            int m = m0+tm+i, n = tn+j;
            float zz = siluf(acc[i][j] + bz[n]);
            g_qrh[(size_t)m*Z_ + n] = __float2half_rn(zz*gamma[n]    + beta[n]);
            g_krh[(size_t)m*Z_ + n] = __float2half_rn(zz*gamma[Z_+n] + beta[Z_+n]);
        }
}

// ---------------- kernel 4: base = x @ Wp^T + bp -> u(fp32), r(half), v(half) ---
__global__ void __launch_bounds__(256, 2) k_base(const float* __restrict__ bp)
{
    extern __shared__ StageH st_dyn[];
    float acc[4][4][4]; ZERO_ACC4(acc);
    const int m0 = blockIdx.y*128, n0 = blockIdx.x*128;
    gemm_nt_h(g_xh, E_, g_Wph, E_, E_, m0, n0, st_dyn, acc);
    EPI2_BEGIN
        float t0 = v0 + bp[col], t1 = v1 + bp[col+1];
        if (col < E_) {
            *(float2*)&g_u[(size_t)row*E_ + col] = make_float2(sigf(t0), sigf(t1));
        } else {
            float s0 = siluf(t0), s1 = siluf(t1);
            int n2 = col - E_;
            if (n2 < H_) *(__half2*)&g_rh[(size_t)row*H_ + n2]      = __floats2half2_rn(s0, s1);
            else         *(__half2*)&g_vh[(size_t)row*H_ + (n2-H_)] = __floats2half2_rn(s0, s1);
        }
    EPI2_END
}

// ---------------- kernel 4b: vT[b][h][l] = v[(l*B+b)][h] ------------------------
__global__ void __launch_bounds__(256) k_vT()
{
    __shared__ __half t[32][33];
    const int b  = blockIdx.z;
    const int h0 = blockIdx.x*32, l0 = blockIdx.y*32;
    const int tx = threadIdx.x & 31, ty = threadIdx.x >> 5;   // 32x8
    #pragma unroll
    for (int i = 0; i < 4; i++) {
        int l = l0 + ty + 8*i;
        t[ty + 8*i][tx] = g_vh[((size_t)l*B_ + b)*H_ + h0 + tx];
    }
    __syncthreads();
    #pragma unroll
    for (int i = 0; i < 4; i++) {
        int h = h0 + ty + 8*i;
        g_vTh[(size_t)b*H_*L_ + (size_t)h*L_ + l0 + tx] = t[tx][ty + 8*i];
    }
}

// ---------------- kernel 5: S = relu(q k^T / L + bias)^2, causal, half out ------
__global__ void __launch_bounds__(256, 2) k_S(const float* __restrict__ rpw)
{
    const int b  = blockIdx.z;
    const int m0 = blockIdx.y*128, n0 = blockIdx.x*128;
    if (n0 > m0) return;
    extern __shared__ StageH st_dyn[];
    float acc[4][4][4]; ZERO_ACC4(acc);
    gemm_nt_h(g_qrh + b*Z_, B_*Z_, g_krh + b*Z_, B_*Z_, Z_, m0, n0, st_dyn, acc);
    __half* Sb = g_Sh + (size_t)b*L_*L_;
    const float inv = 1.f / (float)L_;
    EPI2_BEGIN
        float a0 = v0*inv + rpw[(L_-1) + col   - row];
        float a1 = v1*inv + rpw[(L_-1) + col+1 - row];
        a0 = (col   <= row) ? fmaxf(a0, 0.f) : 0.f;
        a1 = (col+1 <= row) ? fmaxf(a1, 0.f) : 0.f;
        *(__half2*)&Sb[(size_t)row*L_ + col] = __floats2half2_rn(a0*a0, a1*a1);
    EPI2_END
}

// ---------------- kernel 6: hr = (S @ v) * r  (NT with vT, causal K trunc) ------
__global__ void __launch_bounds__(256, 2) k_h()
{
    const int b  = blockIdx.z;
    const int m0 = blockIdx.y*128, n0 = blockIdx.x*128;
    extern __shared__ StageH st_dyn[];
    float acc[4][4][4]; ZERO_ACC4(acc);
    gemm_nt_h(g_Sh + (size_t)b*L_*L_, L_,
              g_vTh + (size_t)b*H_*L_, L_,
              m0 + 128, m0, n0, st_dyn, acc);
    EPI2_BEGIN
        size_t idx = (size_t)(row*B_ + b)*H_ + col;
        __half2 rr = *(const __half2*)&g_rh[idx];
        float2 rf = __half22float2(rr);
        *(__half2*)&g_hrh[idx] = __floats2half2_rn(v0*rf.x, v1*rf.y);
    EPI2_END
}

// ---------------- kernel 7: out = x + u*(tanh(hr Whw^T + mx Whu^T + b) - x) -----
__global__ void __launch_bounds__(256, 2) k_final(const float* __restrict__ x,
        const float* __restrict__ bhw, const float* __restrict__ bhu,
        float* __restrict__ out)
{
    extern __shared__ StageH st_dyn[];
    float acc[4][4][4]; ZERO_ACC4(acc);
    const int m0 = blockIdx.y*128, n0 = blockIdx.x*128;
    gemm_nt_h(g_hrh, H_, g_Whwh, H_, H_, m0, n0, st_dyn, acc);
    gemm_nt_h(g_mxh, Z_, g_Whuh, Z_, Z_, m0, n0, st_dyn, acc);
    EPI2_BEGIN
        float t0 = v0 + bhw[col]   + bhu[col];
        float t1 = v1 + bhw[col+1] + bhu[col+1];
        size_t idx = (size_t)row*E_ + col;
        float2 xv = *(const float2*)&x[idx];
        float2 uu = *(const float2*)&g_u[idx];
        float2 o = make_float2(xv.x + uu.x*(tanhf(t0) - xv.x),
                               xv.y + uu.y*(tanhf(t1) - xv.y));
        *(float2*)&out[idx] = o;
    EPI2_END
}

// -----------------------------------------------------------------------------
extern "C" void kernel_launch(void* const* d_in, const int* in_sizes, int n_in,
                              void* d_out, int out_size)
{
    const float* x     = (const float*)d_in[0];
    const float* delta = (const float*)d_in[2];
    const float* alpha = (const float*)d_in[3];
    const float* ebeta = (const float*)d_in[4];
    const float* egam  = (const float*)d_in[5];
    const float* omega = (const float*)d_in[6];
    const float* Wm    = (const float*)d_in[7];
    const float* bm    = (const float*)d_in[8];
    const float* Wz    = (const float*)d_in[9];
    const float* bz    = (const float*)d_in[10];
    const float* Wp    = (const float*)d_in[11];
    const float* bp    = (const float*)d_in[12];
    const float* Whw   = (const float*)d_in[13];
    const float* bhw   = (const float*)d_in[14];
    const float* Whu   = (const float*)d_in[15];
    const float* bhu   = (const float*)d_in[16];
    const float* gamma = (const float*)d_in[17];
    const float* beta  = (const float*)d_in[18];
    const float* rpw   = (const float*)d_in[19];
    float* out = (float*)d_out;

    __half *xh_p, *Wph_p, *Wmh_p, *Whwh_p, *Whuh_p;
    cudaGetSymbolAddress((void**)&xh_p,   g_xh);
    cudaGetSymbolAddress((void**)&Wph_p,  g_Wph);
    cudaGetSymbolAddress((void**)&Wmh_p,  g_Wmh);
    cudaGetSymbolAddress((void**)&Whwh_p, g_Whwh);
    cudaGetSymbolAddress((void**)&Whuh_p, g_Whuh);

    cudaFuncSetAttribute(k_mx,    cudaFuncAttributeMaxDynamicSharedMemorySize, SMEM_BYTES);
    cudaFuncSetAttribute(k_base,  cudaFuncAttributeMaxDynamicSharedMemorySize, SMEM_BYTES);
    cudaFuncSetAttribute(k_S,     cudaFuncAttributeMaxDynamicSharedMemorySize, SMEM_BYTES);
    cudaFuncSetAttribute(k_h,     cudaFuncAttributeMaxDynamicSharedMemorySize, SMEM_BYTES);
    cudaFuncSetAttribute(k_final, cudaFuncAttributeMaxDynamicSharedMemorySize, SMEM_BYTES);

    static cudaStream_t s2 = nullptr;
    static cudaEvent_t e_fork = nullptr, e_join = nullptr;
    if (s2 == nullptr) {
        cudaStreamCreateWithFlags(&s2, cudaStreamNonBlocking);
        cudaEventCreateWithFlags(&e_fork, cudaEventDisableTiming);
        cudaEventCreateWithFlags(&e_join, cudaEventDisableTiming);
    }

    cudaEventRecord(e_fork, 0);
    cudaStreamWaitEvent(s2, e_fork, 0);

    // ---- branch A on s2: cvt(x, Wp) -> k_base -> k_vT ----
    k_cvt <<<MB_*E_/1024, 256, 0, s2>>>(x,  xh_p);
    k_cvt <<<(E_+2*H_)*E_/1024, 256, 0, s2>>>(Wp, Wph_p);
    k_base<<<dim3(40, 128), 256, SMEM_BYTES, s2>>>(bp);
    k_vT  <<<dim3(H_/32, L_/32, B_), 256, 0, s2>>>();
    cudaEventRecord(e_join, s2);

    // ---- branch B on default stream ----
    k_cvt  <<<Z_*E_/1024, 256>>>(Wm,  Wmh_p);
    k_cvt  <<<E_*H_/1024, 256>>>(Whw, Whwh_p);
    k_cvt  <<<E_*Z_/1024, 256>>>(Whu, Whuh_p);
    k_ema_a<<<CH_*B_*E_/256, 256>>>(x, delta, alpha);
    k_ema_b<<<B_*E_/256, 256>>>(delta, alpha);
    k_ema_c<<<CH_*B_*E_/256, 256>>>(x, delta, alpha, ebeta, egam, omega);
    k_mx   <<<dim3(1, 128),    256, SMEM_BYTES>>>(bm);
    k_z    <<<dim3(1, 128),    256>>>(Wz, bz, gamma, beta);
    k_S    <<<dim3(16, 16, 8), 256, SMEM_BYTES>>>(rpw);

    // ---- join: k_h needs S (B) + vT, r (A) ----
    cudaStreamWaitEvent(0, e_join, 0);
    k_h    <<<dim3(16, 16, 8), 256, SMEM_BYTES>>>();
    k_final<<<dim3(8, 128),    256, SMEM_BYTES>>>(x, bhw, bhu, out);
}

// round 16
// speedup vs baseline: 1.1627x; 1.0173x over previous
#include <cuda_runtime.h>
#include <cuda_fp16.h>
#include <math.h>
#include <stdint.h>

#define L_  2048
#define B_  8
#define E_  1024
#define Z_  128
#define H_  2048
#define MB_ (L_*B_)   // 16384 rows
#define CH_ 32        // ema chunks
#define CL_ (L_/CH_)  // 64 steps per chunk

// ---------------- scratch (static device allocations; no cudaMalloc) ----------
__device__ __half g_xh  [MB_*E_];
__device__ __half g_emah[MB_*E_];
__device__ float  g_mx  [MB_*Z_];
__device__ __half g_mxh [MB_*Z_];
__device__ __half g_qrh [MB_*Z_];
__device__ __half g_krh [MB_*Z_];
__device__ float  g_u   [MB_*E_];
__device__ float  g_hu  [MB_*E_];   // mx@Whu^T + bhw + bhu (precomputed)
__device__ __half g_rh  [MB_*H_];
__device__ __half g_vh  [MB_*H_];
__device__ __half g_vTh [(size_t)B_*H_*L_];
__device__ __half g_Sh  [(size_t)B_*L_*L_];
__device__ __half g_hrh [MB_*H_];
__device__ float  g_hend[2*CH_*B_*E_];
__device__ float  g_cin [2*CH_*B_*E_];
// half weights
__device__ __half g_Wph [(E_+2*H_)*E_];
__device__ __half g_Wmh [Z_*E_];
__device__ __half g_Whwh[E_*H_];
__device__ __half g_Whuh[E_*Z_];

__device__ __forceinline__ float sigf (float v){ return 1.f/(1.f+expf(-v)); }
__device__ __forceinline__ float siluf(float v){ return v/(1.f+expf(-v)); }

// ---------------- async / mma helpers -----------------------------------------
#define CP_A16(dst_u32, src_ptr) \
    asm volatile("cp.async.ca.shared.global [%0], [%1], 16;\n" :: "r"(dst_u32), "l"(src_ptr) : "memory")
#define CP_COMMIT() asm volatile("cp.async.commit_group;\n" ::: "memory")
#define CP_WAIT(N)  asm volatile("cp.async.wait_group %0;\n" :: "n"(N) : "memory")

__device__ __forceinline__ void ldsm4(uint32_t (&r)[4], uint32_t addr) {
    asm volatile("ldmatrix.sync.aligned.m8n8.x4.shared.b16 {%0,%1,%2,%3}, [%4];"
        : "=r"(r[0]), "=r"(r[1]), "=r"(r[2]), "=r"(r[3]) : "r"(addr));
}
__device__ __forceinline__ void mma16(float (&c)[4], const uint32_t (&a)[4],
                                      uint32_t b0, uint32_t b1) {
    asm volatile(
        "mma.sync.aligned.m16n8k16.row.col.f32.f16.f16.f32 "
        "{%0,%1,%2,%3},{%4,%5,%6,%7},{%8,%9},{%0,%1,%2,%3};\n"
        : "+f"(c[0]), "+f"(c[1]), "+f"(c[2]), "+f"(c[3])
        : "r"(a[0]), "r"(a[1]), "r"(a[2]), "r"(a[3]), "r"(b0), "r"(b1));
}

// ---------------- fp16 NT gemm core (round-13 proven config) -------------------
// block tile 128x128, 256 threads, 8 warps (2x4), warp tile 64x32,
// BK=64 halves, 2-stage cp.async ring, padded 144B pitch. 2 CTAs/SM.

struct StageH { __half A[128][72]; __half B[128][72]; };   // 144B row pitch
#define SMEM_BYTES (2*(int)sizeof(StageH))

// load 128 rows x 64 halves (128B) tile; 1024 16B-chunks, 256 threads -> 4 each
__device__ __forceinline__ void cpa_h(__half (*t)[72], const __half* __restrict__ src,
                                      int ld, int r0, int k0, int tid) {
    #pragma unroll
    for (int it = 0; it < 4; it++) {
        int i = tid + 256*it;
        int row = i >> 3, c = i & 7;
        uint32_t dst = (uint32_t)__cvta_generic_to_shared(&t[row][c*8]);
        CP_A16(dst, src + (size_t)(r0+row)*ld + k0 + c*8);
    }
}

// C += A(M,K) * B(N,K)^T ; K multiple of 64, K/64 >= 2
__device__ __forceinline__ void gemm_nt_h(const __half* __restrict__ A, int lda,
                                          const __half* __restrict__ B, int ldb,
                                          int K, int m0, int n0,
                                          StageH* st, float (&acc)[4][4][4]) {
    const int tid = threadIdx.x;
    const int wid = tid >> 5, lane = tid & 31;
    const int wm = (wid >> 2) * 64, wn = (wid & 3) * 32;
    const int nk = K >> 6;
    cpa_h(st[0].A, A, lda, m0, 0, tid);
    cpa_h(st[0].B, B, ldb, n0, 0, tid);
    CP_COMMIT();
    for (int i = 0; i < nk; i++) {
        const int cur = i & 1;
        CP_WAIT(0);               // all loads (stage i included) complete
        __syncthreads();          // data visible; all warps past mma(i-1) on buf cur^1
        if (i + 1 < nk) {
            cpa_h(st[cur^1].A, A, lda, m0, (i+1)<<6, tid);
            cpa_h(st[cur^1].B, B, ldb, n0, (i+1)<<6, tid);
            CP_COMMIT();
        }
        StageH& s = st[cur];
        uint32_t abase = (uint32_t)__cvta_generic_to_shared(&s.A[wm + (lane & 15)][(lane >> 4) * 8]);
        uint32_t bbase = (uint32_t)__cvta_generic_to_shared(&s.B[wn + (lane & 15)][(lane >> 4) * 8]);
        #pragma unroll
        for (int kk = 0; kk < 4; kk++) {            // four k16 sub-steps (32B each)
            uint32_t a[4][4], bf[2][4];
            #pragma unroll
            for (int mt = 0; mt < 4; mt++) ldsm4(a[mt],  abase + mt*16*144 + kk*32);
            #pragma unroll
            for (int np = 0; np < 2; np++) ldsm4(bf[np], bbase + np*16*144 + kk*32);
            #pragma unroll
            for (int nt = 0; nt < 4; nt++) {
                uint32_t b0 = bf[nt >> 1][nt & 1];
                uint32_t b1 = bf[nt >> 1][2 + (nt & 1)];
                #pragma unroll
                for (int mt = 0; mt < 4; mt++) mma16(acc[mt][nt], a[mt], b0, b1);
            }
        }
    }
    __syncthreads();              // protect ring reuse by a following gemm call
}

#define ZERO_ACC4(acc) { _Pragma("unroll") for (int i=0;i<4;i++) _Pragma("unroll") for (int j=0;j<4;j++) _Pragma("unroll") for (int q=0;q<4;q++) acc[i][j][q]=0.f; }

// epilogue pairs: (row, col) with v0, v1 at columns col, col+1 (col even)
#define EPI2_BEGIN \
    { const int wid_ = threadIdx.x >> 5, lane_ = threadIdx.x & 31; \
      const int wm_ = (wid_ >> 2)*64, wn_ = (wid_ & 3)*32; \
      const int g_ = lane_ >> 2, t_ = lane_ & 3; \
      _Pragma("unroll") for (int mt = 0; mt < 4; mt++) \
      _Pragma("unroll") for (int nt = 0; nt < 4; nt++) \
      _Pragma("unroll") for (int hq = 0; hq < 2; hq++) { \
          int row = m0 + wm_ + mt*16 + g_ + 8*hq; \
          int col = n0 + wn_ + nt*8 + 2*t_; \
          float v0 = acc[mt][nt][2*hq], v1 = acc[mt][nt][2*hq+1];
#define EPI2_END } }

// ---------------- fp32 -> fp16 conversion --------------------------------------
__global__ void __launch_bounds__(256) k_cvt(const float* __restrict__ s,
                                             __half* __restrict__ d) {
    int i = (blockIdx.x*256 + threadIdx.x) * 4;
    float4 f = *(const float4*)(s + i);
    *(__half2*)(d + i)     = __floats2half2_rn(f.x, f.y);
    *(__half2*)(d + i + 2) = __floats2half2_rn(f.z, f.w);
}

// ---------------- EMA: 3-phase chunked linear scan -----------------------------
__device__ __forceinline__ void ema_params(int e, const float* delta, const float* alpha,
        float& q0, float& q1) {
    float p0 = sigf(delta[e*2+0]);
    float p1 = sigf(delta[e*2+1]);
    q0 = 1.f - p0*sigf(alpha[e*2+0]);
    q1 = 1.f - p1*sigf(alpha[e*2+1]);
}

__global__ void __launch_bounds__(256) k_ema_a(const float* __restrict__ x,
        const float* __restrict__ delta, const float* __restrict__ alpha)
{
    const int gt = blockIdx.x*256 + threadIdx.x;
    const int be = gt & (B_*E_-1);
    const int c  = gt >> 13;
    const int e  = be & (E_-1);
    float q0, q1; ema_params(e, delta, alpha, q0, q1);
    float h0 = 0.f, h1 = 0.f;
    const float* xp = x + (size_t)(c*CL_)*(B_*E_) + be;
    #pragma unroll 4
    for (int l = 0; l < CL_; l++) {
        float xv = xp[(size_t)l*(B_*E_)];
        h0 = q0*h0 + xv;
        h1 = q1*h1 + xv;
    }
    g_hend[(size_t)c*(B_*E_) + be]       = h0;
    g_hend[(size_t)(CH_+c)*(B_*E_) + be] = h1;
}

__global__ void __launch_bounds__(256) k_ema_b(const float* __restrict__ delta,
        const float* __restrict__ alpha)
{
    const int be = blockIdx.x*256 + threadIdx.x;
    const int e  = be & (E_-1);
    float q0, q1; ema_params(e, delta, alpha, q0, q1);
    float qp0 = q0, qp1 = q1;
    #pragma unroll
    for (int i = 0; i < 6; i++) { qp0 *= qp0; qp1 *= qp1; }   // q^64
    float c0 = 0.f, c1 = 0.f;
    for (int c = 0; c < CH_; c++) {
        g_cin[(size_t)c*(B_*E_) + be]       = c0;
        g_cin[(size_t)(CH_+c)*(B_*E_) + be] = c1;
        c0 = qp0*c0 + g_hend[(size_t)c*(B_*E_) + be];
        c1 = qp1*c1 + g_hend[(size_t)(CH_+c)*(B_*E_) + be];
    }
}

__global__ void __launch_bounds__(256) k_ema_c(const float* __restrict__ x,
        const float* __restrict__ delta, const float* __restrict__ alpha,
        const float* __restrict__ ebeta, const float* __restrict__ egam,
        const float* __restrict__ omega)
{
    const int gt = blockIdx.x*256 + threadIdx.x;
    const int be = gt & (B_*E_-1);
    const int c  = gt >> 13;
    const int e  = be & (E_-1);
    float p0 = sigf(delta[e*2+0]);
    float p1 = sigf(delta[e*2+1]);
    float q0 = 1.f - p0*sigf(alpha[e*2+0]);
    float q1 = 1.f - p1*sigf(alpha[e*2+1]);
    const float sc = 0.70710678118654752f;
    float c0 = p0*ebeta[e*2+0]*egam[e*2+0]*sc;
    float c1 = p1*ebeta[e*2+1]*egam[e*2+1]*sc;
    float om = omega[e];
    float h0 = g_cin[(size_t)c*(B_*E_) + be];
    float h1 = g_cin[(size_t)(CH_+c)*(B_*E_) + be];
    const size_t base = (size_t)(c*CL_)*(B_*E_) + be;
    #pragma unroll 4
    for (int l = 0; l < CL_; l++) {
        float xv = x[base + (size_t)l*(B_*E_)];
        h0 = q0*h0 + xv;
        h1 = q1*h1 + xv;
        float o = c0*h0 + c1*h1 + xv*om;
        g_emah[base + (size_t)l*(B_*E_)] = __float2half_rn(siluf(o));
    }
}

// ---------------- kernel 2: mx = ema @ Wm^T + bm (fp32 + half outputs) ----------
__global__ void __launch_bounds__(256, 2) k_mx(const float* __restrict__ bm)
{
    extern __shared__ StageH st_dyn[];
    float acc[4][4][4]; ZERO_ACC4(acc);
    const int m0 = blockIdx.y*128, n0 = blockIdx.x*128;
    gemm_nt_h(g_emah, E_, g_Wmh, E_, E_, m0, n0, st_dyn, acc);
    EPI2_BEGIN
        float o0 = v0 + bm[col], o1 = v1 + bm[col+1];
        *(float2*)&g_mx[(size_t)row*Z_ + col] = make_float2(o0, o1);
        *(__half2*)&g_mxh[(size_t)row*Z_ + col] = __floats2half2_rn(o0, o1);
    EPI2_END
}

// ---------------- kernel 2b: hu = mx @ Whu^T + bhw + bhu (branch B) -------------
__global__ void __launch_bounds__(256, 2) k_hu(const float* __restrict__ bhw,
                                               const float* __restrict__ bhu)
{
    extern __shared__ StageH st_dyn[];
    float acc[4][4][4]; ZERO_ACC4(acc);
    const int m0 = blockIdx.y*128, n0 = blockIdx.x*128;
    gemm_nt_h(g_mxh, Z_, g_Whuh, Z_, Z_, m0, n0, st_dyn, acc);
    EPI2_BEGIN
        float o0 = v0 + bhw[col]   + bhu[col];
        float o1 = v1 + bhw[col+1] + bhu[col+1];
        *(float2*)&g_hu[(size_t)row*E_ + col] = make_float2(o0, o1);
    EPI2_END
}

// ---------------- kernel 3: z (fp32 FFMA for precision; tiny) -------------------
struct TilesF { float As[16][132]; float Bs[16][132]; };
__global__ void __launch_bounds__(256) k_z(const float* __restrict__ Wz,
        const float* __restrict__ bz, const float* __restrict__ gamma,
        const float* __restrict__ beta)
{
    __shared__ TilesF s;
    float acc[8][8];
    #pragma unroll
    for (int i=0;i<8;i++)
        #pragma unroll
        for (int j=0;j<8;j++) acc[i][j]=0.f;
    const int m0 = blockIdx.y*128;
    const int tid = threadIdx.x;
    const int tm = (tid >> 4) << 3, tn = (tid & 15) << 3;
    for (int k0 = 0; k0 < Z_; k0 += 16) {
        #pragma unroll
        for (int j = 0; j < 8; j++) {
            int i = tid + 256*j;
            int row = i >> 4, kk = i & 15;
            s.As[kk][row] = g_mx[(size_t)(m0+row)*Z_ + k0 + kk];
            s.Bs[kk][row] = Wz[(size_t)row*Z_ + k0 + kk];
        }
        __syncthreads();
        #pragma unroll
        for (int kk = 0; kk < 16; kk++) {
            float a[8], b[8];
            *(float4*)&a[0] = *(const float4*)&s.As[kk][tm];
            *(float4*)&a[4] = *(const float4*)&s.As[kk][tm+4];
            *(float4*)&b[0] = *(const float4*)&s.Bs[kk][tn];
            *(float4*)&b[4] = *(const float4*)&s.Bs[kk][tn+4];
            #pragma unroll
            for (int i = 0; i < 8; i++)
                #pragma unroll
                for (int j = 0; j < 8; j++)
                    acc[i][j] += a[i]*b[j];
        }
        __syncthreads();
    }
    #pragma unroll
    for (int i = 0; i < 8; i++)
        #pragma unroll
        for (int j = 0; j < 8; j++) {
            int m = m0+tm+i, n = tn+j;
            float zz = siluf(acc[i][j] + bz[n]);
            g_qrh[(size_t)m*Z_ + n] = __float2half_rn(zz*gamma[n]    + beta[n]);
            g_krh[(size_t)m*Z_ + n] = __float2half_rn(zz*gamma[Z_+n] + beta[Z_+n]);
        }
}

// ---------------- kernel 4: base = x @ Wp^T + bp -> u(fp32), r(half), v(half) ---
__global__ void __launch_bounds__(256, 2) k_base(const float* __restrict__ bp)
{
    extern __shared__ StageH st_dyn[];
    float acc[4][4][4]; ZERO_ACC4(acc);
    const int m0 = blockIdx.y*128, n0 = blockIdx.x*128;
    gemm_nt_h(g_xh, E_, g_Wph, E_, E_, m0, n0, st_dyn, acc);
    EPI2_BEGIN
        float t0 = v0 + bp[col], t1 = v1 + bp[col+1];
        if (col < E_) {
            *(float2*)&g_u[(size_t)row*E_ + col] = make_float2(sigf(t0), sigf(t1));
        } else {
            float s0 = siluf(t0), s1 = siluf(t1);
            int n2 = col - E_;
            if (n2 < H_) *(__half2*)&g_rh[(size_t)row*H_ + n2]      = __floats2half2_rn(s0, s1);
            else         *(__half2*)&g_vh[(size_t)row*H_ + (n2-H_)] = __floats2half2_rn(s0, s1);
        }
    EPI2_END
}

// ---------------- kernel 4b: vT[b][h][l] = v[(l*B+b)][h] ------------------------
__global__ void __launch_bounds__(256) k_vT()
{
    __shared__ __half t[32][33];
    const int b  = blockIdx.z;
    const int h0 = blockIdx.x*32, l0 = blockIdx.y*32;
    const int tx = threadIdx.x & 31, ty = threadIdx.x >> 5;   // 32x8
    #pragma unroll
    for (int i = 0; i < 4; i++) {
        int l = l0 + ty + 8*i;
        t[ty + 8*i][tx] = g_vh[((size_t)l*B_ + b)*H_ + h0 + tx];
    }
    __syncthreads();
    #pragma unroll
    for (int i = 0; i < 4; i++) {
        int h = h0 + ty + 8*i;
        g_vTh[(size_t)b*H_*L_ + (size_t)h*L_ + l0 + tx] = t[tx][ty + 8*i];
    }
}

// ---------------- kernel 5: S = relu(q k^T / L + bias)^2, causal, half out ------
__global__ void __launch_bounds__(256, 2) k_S(const float* __restrict__ rpw)
{
    const int b  = blockIdx.z;
    const int m0 = blockIdx.y*128, n0 = blockIdx.x*128;
    if (n0 > m0) return;
    extern __shared__ StageH st_dyn[];
    float acc[4][4][4]; ZERO_ACC4(acc);
    gemm_nt_h(g_qrh + b*Z_, B_*Z_, g_krh + b*Z_, B_*Z_, Z_, m0, n0, st_dyn, acc);
    __half* Sb = g_Sh + (size_t)b*L_*L_;
    const float inv = 1.f / (float)L_;
    EPI2_BEGIN
        float a0 = v0*inv + rpw[(L_-1) + col   - row];
        float a1 = v1*inv + rpw[(L_-1) + col+1 - row];
        a0 = (col   <= row) ? fmaxf(a0, 0.f) : 0.f;
        a1 = (col+1 <= row) ? fmaxf(a1, 0.f) : 0.f;
        *(__half2*)&Sb[(size_t)row*L_ + col] = __floats2half2_rn(a0*a0, a1*a1);
    EPI2_END
}

// ---------------- kernel 6: hr = (S @ v) * r  (NT with vT, causal K trunc) ------
__global__ void __launch_bounds__(256, 2) k_h()
{
    const int b  = blockIdx.z;
    const int m0 = blockIdx.y*128, n0 = blockIdx.x*128;
    extern __shared__ StageH st_dyn[];
    float acc[4][4][4]; ZERO_ACC4(acc);
    gemm_nt_h(g_Sh + (size_t)b*L_*L_, L_,
              g_vTh + (size_t)b*H_*L_, L_,
              m0 + 128, m0, n0, st_dyn, acc);
    EPI2_BEGIN
        size_t idx = (size_t)(row*B_ + b)*H_ + col;
        __half2 rr = *(const __half2*)&g_rh[idx];
        float2 rf = __half22float2(rr);
        *(__half2*)&g_hrh[idx] = __floats2half2_rn(v0*rf.x, v1*rf.y);
    EPI2_END
}

// ---------------- kernel 7: out = x + u*(tanh(hr Whw^T + hu) - x) ---------------
__global__ void __launch_bounds__(256, 2) k_final(const float* __restrict__ x,
        float* __restrict__ out)
{
    extern __shared__ StageH st_dyn[];
    float acc[4][4][4]; ZERO_ACC4(acc);
    const int m0 = blockIdx.y*128, n0 = blockIdx.x*128;
    gemm_nt_h(g_hrh, H_, g_Whwh, H_, H_, m0, n0, st_dyn, acc);
    EPI2_BEGIN
        size_t idx = (size_t)row*E_ + col;
        float2 hu = *(const float2*)&g_hu[idx];
        float t0 = v0 + hu.x, t1 = v1 + hu.y;
        float2 xv = *(const float2*)&x[idx];
        float2 uu = *(const float2*)&g_u[idx];
        float2 o = make_float2(xv.x + uu.x*(tanhf(t0) - xv.x),
                               xv.y + uu.y*(tanhf(t1) - xv.y));
        *(float2*)&out[idx] = o;
    EPI2_END
}

// -----------------------------------------------------------------------------
extern "C" void kernel_launch(void* const* d_in, const int* in_sizes, int n_in,
                              void* d_out, int out_size)
{
    const float* x     = (const float*)d_in[0];
    const float* delta = (const float*)d_in[2];
    const float* alpha = (const float*)d_in[3];
    const float* ebeta = (const float*)d_in[4];
    const float* egam  = (const float*)d_in[5];
    const float* omega = (const float*)d_in[6];
    const float* Wm    = (const float*)d_in[7];
    const float* bm    = (const float*)d_in[8];
    const float* Wz    = (const float*)d_in[9];
    const float* bz    = (const float*)d_in[10];
    const float* Wp    = (const float*)d_in[11];
    const float* bp    = (const float*)d_in[12];
    const float* Whw   = (const float*)d_in[13];
    const float* bhw   = (const float*)d_in[14];
    const float* Whu   = (const float*)d_in[15];
    const float* bhu   = (const float*)d_in[16];
    const float* gamma = (const float*)d_in[17];
    const float* beta  = (const float*)d_in[18];
    const float* rpw   = (const float*)d_in[19];
    float* out = (float*)d_out;

    __half *xh_p, *Wph_p, *Wmh_p, *Whwh_p, *Whuh_p;
    cudaGetSymbolAddress((void**)&xh_p,   g_xh);
    cudaGetSymbolAddress((void**)&Wph_p,  g_Wph);
    cudaGetSymbolAddress((void**)&Wmh_p,  g_Wmh);
    cudaGetSymbolAddress((void**)&Whwh_p, g_Whwh);
    cudaGetSymbolAddress((void**)&Whuh_p, g_Whuh);

    cudaFuncSetAttribute(k_mx,    cudaFuncAttributeMaxDynamicSharedMemorySize, SMEM_BYTES);
    cudaFuncSetAttribute(k_hu,    cudaFuncAttributeMaxDynamicSharedMemorySize, SMEM_BYTES);
    cudaFuncSetAttribute(k_base,  cudaFuncAttributeMaxDynamicSharedMemorySize, SMEM_BYTES);
    cudaFuncSetAttribute(k_S,     cudaFuncAttributeMaxDynamicSharedMemorySize, SMEM_BYTES);
    cudaFuncSetAttribute(k_h,     cudaFuncAttributeMaxDynamicSharedMemorySize, SMEM_BYTES);
    cudaFuncSetAttribute(k_final, cudaFuncAttributeMaxDynamicSharedMemorySize, SMEM_BYTES);

    static cudaStream_t s2 = nullptr;
    static cudaEvent_t e_fork = nullptr, e_join = nullptr;
    if (s2 == nullptr) {
        cudaStreamCreateWithFlags(&s2, cudaStreamNonBlocking);
        cudaEventCreateWithFlags(&e_fork, cudaEventDisableTiming);
        cudaEventCreateWithFlags(&e_join, cudaEventDisableTiming);
    }

    cudaEventRecord(e_fork, 0);
    cudaStreamWaitEvent(s2, e_fork, 0);

    // ---- branch A on s2: cvt(x, Wp) -> k_base -> k_vT ----
    k_cvt <<<MB_*E_/1024, 256, 0, s2>>>(x,  xh_p);
    k_cvt <<<(E_+2*H_)*E_/1024, 256, 0, s2>>>(Wp, Wph_p);
    k_base<<<dim3(40, 128), 256, SMEM_BYTES, s2>>>(bp);
    k_vT  <<<dim3(H_/32, L_/32, B_), 256, 0, s2>>>();
    cudaEventRecord(e_join, s2);

    // ---- branch B on default stream ----
    k_cvt  <<<Z_*E_/1024, 256>>>(Wm,  Wmh_p);
    k_cvt  <<<E_*H_/1024, 256>>>(Whw, Whwh_p);
    k_cvt  <<<E_*Z_/1024, 256>>>(Whu, Whuh_p);
    k_ema_a<<<CH_*B_*E_/256, 256>>>(x, delta, alpha);
    k_ema_b<<<B_*E_/256, 256>>>(delta, alpha);
    k_ema_c<<<CH_*B_*E_/256, 256>>>(x, delta, alpha, ebeta, egam, omega);
    k_mx   <<<dim3(1, 128),    256, SMEM_BYTES>>>(bm);
    k_hu   <<<dim3(8, 128),    256, SMEM_BYTES>>>(bhw, bhu);
    k_z    <<<dim3(1, 128),    256>>>(Wz, bz, gamma, beta);
    k_S    <<<dim3(16, 16, 8), 256, SMEM_BYTES>>>(rpw);

    // ---- join: k_h needs S (B) + vT, r (A) ----
    cudaStreamWaitEvent(0, e_join, 0);
    k_h    <<<dim3(16, 16, 8), 256, SMEM_BYTES>>>();
    k_final<<<dim3(8, 128),    256, SMEM_BYTES>>>(x, out);
}

// round 17
// speedup vs baseline: 1.2144x; 1.0445x over previous
#include <cuda_runtime.h>
#include <cuda_fp16.h>
#include <math.h>
#include <stdint.h>

#define L_  2048
#define B_  8
#define E_  1024
#define Z_  128
#define H_  2048
#define MB_ (L_*B_)   // 16384 rows
#define CH_ 32        // ema chunks
#define CL_ (L_/CH_)  // 64 steps per chunk

// ---------------- scratch (static device allocations; no cudaMalloc) ----------
__device__ __half g_xh  [MB_*E_];
__device__ __half g_emah[MB_*E_];
__device__ float  g_mx  [MB_*Z_];
__device__ __half g_mxh [MB_*Z_];
__device__ __half g_qrh [MB_*Z_];
__device__ __half g_krh [MB_*Z_];
__device__ float  g_u   [MB_*E_];
__device__ __half g_rh  [MB_*H_];
__device__ __half g_vh  [MB_*H_];
__device__ __half g_Sh  [(size_t)B_*L_*L_];
__device__ __half g_hrh [MB_*H_];
__device__ float  g_hend[2*CH_*B_*E_];
__device__ float  g_cin [2*CH_*B_*E_];
// half weights
__device__ __half g_Wph [(E_+2*H_)*E_];
__device__ __half g_Wmh [Z_*E_];
__device__ __half g_Whwh[E_*H_];
__device__ __half g_Whuh[E_*Z_];

__device__ __forceinline__ float sigf (float v){ return 1.f/(1.f+expf(-v)); }
__device__ __forceinline__ float siluf(float v){ return v/(1.f+expf(-v)); }

// ---------------- async / mma helpers -----------------------------------------
#define CP_A16(dst_u32, src_ptr) \
    asm volatile("cp.async.ca.shared.global [%0], [%1], 16;\n" :: "r"(dst_u32), "l"(src_ptr) : "memory")
#define CP_COMMIT() asm volatile("cp.async.commit_group;\n" ::: "memory")
#define CP_WAIT(N)  asm volatile("cp.async.wait_group %0;\n" :: "n"(N) : "memory")

__device__ __forceinline__ void ldsm4(uint32_t (&r)[4], uint32_t addr) {
    asm volatile("ldmatrix.sync.aligned.m8n8.x4.shared.b16 {%0,%1,%2,%3}, [%4];"
        : "=r"(r[0]), "=r"(r[1]), "=r"(r[2]), "=r"(r[3]) : "r"(addr));
}
__device__ __forceinline__ void ldsm4t(uint32_t (&r)[4], uint32_t addr) {
    asm volatile("ldmatrix.sync.aligned.m8n8.x4.trans.shared.b16 {%0,%1,%2,%3}, [%4];"
        : "=r"(r[0]), "=r"(r[1]), "=r"(r[2]), "=r"(r[3]) : "r"(addr));
}
__device__ __forceinline__ void mma16(float (&c)[4], const uint32_t (&a)[4],
                                      uint32_t b0, uint32_t b1) {
    asm volatile(
        "mma.sync.aligned.m16n8k16.row.col.f32.f16.f16.f32 "
        "{%0,%1,%2,%3},{%4,%5,%6,%7},{%8,%9},{%0,%1,%2,%3};\n"
        : "+f"(c[0]), "+f"(c[1]), "+f"(c[2]), "+f"(c[3])
        : "r"(a[0]), "r"(a[1]), "r"(a[2]), "r"(a[3]), "r"(b0), "r"(b1));
}

// ---------------- fp16 gemm cores (round-13 proven config) ---------------------
// block tile 128x128, 256 threads, 8 warps (2x4), warp tile 64x32,
// BK=64 halves, 2-stage cp.async ring, padded pitches. 2 CTAs/SM.

struct StageH { __half A[128][72]; __half B[128][72]; };            // NT: 36.9KB
struct StageN { __half A[128][72]; __half B[64][136]; };            // NN: 35.8KB
#define SMEM_BYTES  (2*(int)sizeof(StageH))
#define SMEMN_BYTES (2*(int)sizeof(StageN))

// load 128 rows x 64 halves (128B) tile; 1024 16B-chunks, 256 threads -> 4 each
__device__ __forceinline__ void cpa_h(__half (*t)[72], const __half* __restrict__ src,
                                      int ld, int r0, int k0, int tid) {
    #pragma unroll
    for (int it = 0; it < 4; it++) {
        int i = tid + 256*it;
        int row = i >> 3, c = i & 7;
        uint32_t dst = (uint32_t)__cvta_generic_to_shared(&t[row][c*8]);
        CP_A16(dst, src + (size_t)(r0+row)*ld + k0 + c*8);
    }
}
// NN B loader: 64 k-rows x 128 n-cols (src pre-offset to n0); 1024 chunks
__device__ __forceinline__ void cpa_b_nn(__half (*t)[136], const __half* __restrict__ src,
                                         size_t ldb, int k0, int tid) {
    #pragma unroll
    for (int it = 0; it < 4; it++) {
        int i = tid + 256*it;
        int row = i >> 4, c = i & 15;
        uint32_t dst = (uint32_t)__cvta_generic_to_shared(&t[row][c*8]);
        CP_A16(dst, src + (size_t)(k0+row)*ldb + c*8);
    }
}

// C += A(M,K) * B(N,K)^T ; K multiple of 64, K/64 >= 2
__device__ __forceinline__ void gemm_nt_h(const __half* __restrict__ A, int lda,
                                          const __half* __restrict__ B, int ldb,
                                          int K, int m0, int n0,
                                          StageH* st, float (&acc)[4][4][4]) {
    const int tid = threadIdx.x;
    const int wid = tid >> 5, lane = tid & 31;
    const int wm = (wid >> 2) * 64, wn = (wid & 3) * 32;
    const int nk = K >> 6;
    cpa_h(st[0].A, A, lda, m0, 0, tid);
    cpa_h(st[0].B, B, ldb, n0, 0, tid);
    CP_COMMIT();
    for (int i = 0; i < nk; i++) {
        const int cur = i & 1;
        CP_WAIT(0);
        __syncthreads();
        if (i + 1 < nk) {
            cpa_h(st[cur^1].A, A, lda, m0, (i+1)<<6, tid);
            cpa_h(st[cur^1].B, B, ldb, n0, (i+1)<<6, tid);
            CP_COMMIT();
        }
        StageH& s = st[cur];
        uint32_t abase = (uint32_t)__cvta_generic_to_shared(&s.A[wm + (lane & 15)][(lane >> 4) * 8]);
        uint32_t bbase = (uint32_t)__cvta_generic_to_shared(&s.B[wn + (lane & 15)][(lane >> 4) * 8]);
        #pragma unroll
        for (int kk = 0; kk < 4; kk++) {
            uint32_t a[4][4], bf[2][4];
            #pragma unroll
            for (int mt = 0; mt < 4; mt++) ldsm4(a[mt],  abase + mt*16*144 + kk*32);
            #pragma unroll
            for (int np = 0; np < 2; np++) ldsm4(bf[np], bbase + np*16*144 + kk*32);
            #pragma unroll
            for (int nt = 0; nt < 4; nt++) {
                uint32_t b0 = bf[nt >> 1][nt & 1];
                uint32_t b1 = bf[nt >> 1][2 + (nt & 1)];
                #pragma unroll
                for (int mt = 0; mt < 4; mt++) mma16(acc[mt][nt], a[mt], b0, b1);
            }
        }
    }
    __syncthreads();
}

// C += A(M,K) * B(K,N) ; B natural k-major (src pre-offset to n0); K mult of 64
__device__ __forceinline__ void gemm_nn_h(const __half* __restrict__ A, int lda,
                                          const __half* __restrict__ Bsrc, size_t ldb,
                                          int K, int m0,
                                          StageN* st, float (&acc)[4][4][4]) {
    const int tid = threadIdx.x;
    const int wid = tid >> 5, lane = tid & 31;
    const int wm = (wid >> 2) * 64, wn = (wid & 3) * 32;
    const int nk = K >> 6;
    cpa_h   (st[0].A, A, lda, m0, 0, tid);
    cpa_b_nn(st[0].B, Bsrc, ldb, 0, tid);
    CP_COMMIT();
    // trans B fragment address: row = (lane&7) + 8*(lane>>4) [k within 16],
    // col halves = wn + 8*((lane>>3)&1)
    const uint32_t brow = (uint32_t)((lane & 7) + ((lane >> 4) << 3));
    for (int i = 0; i < nk; i++) {
        const int cur = i & 1;
        CP_WAIT(0);
        __syncthreads();
        if (i + 1 < nk) {
            cpa_h   (st[cur^1].A, A, lda, m0, (i+1)<<6, tid);
            cpa_b_nn(st[cur^1].B, Bsrc, ldb, (i+1)<<6, tid);
            CP_COMMIT();
        }
        StageN& s = st[cur];
        uint32_t abase = (uint32_t)__cvta_generic_to_shared(&s.A[wm + (lane & 15)][(lane >> 4) * 8]);
        uint32_t bbase = (uint32_t)__cvta_generic_to_shared(s.B)
                       + brow*272u + (uint32_t)(wn + (((lane >> 3) & 1) << 3))*2u;
        #pragma unroll
        for (int kk = 0; kk < 4; kk++) {
            uint32_t a[4][4], bf[2][4];
            #pragma unroll
            for (int mt = 0; mt < 4; mt++) ldsm4(a[mt], abase + mt*16*144 + kk*32);
            #pragma unroll
            for (int np = 0; np < 2; np++) ldsm4t(bf[np], bbase + (uint32_t)kk*16u*272u + (uint32_t)np*32u);
            #pragma unroll
            for (int nt = 0; nt < 4; nt++) {
                uint32_t b0 = bf[nt >> 1][nt & 1];
                uint32_t b1 = bf[nt >> 1][2 + (nt & 1)];
                #pragma unroll
                for (int mt = 0; mt < 4; mt++) mma16(acc[mt][nt], a[mt], b0, b1);
            }
        }
    }
    __syncthreads();
}

#define ZERO_ACC4(acc) { _Pragma("unroll") for (int i=0;i<4;i++) _Pragma("unroll") for (int j=0;j<4;j++) _Pragma("unroll") for (int q=0;q<4;q++) acc[i][j][q]=0.f; }

// epilogue pairs: (row, col) with v0, v1 at columns col, col+1 (col even)
#define EPI2_BEGIN \
    { const int wid_ = threadIdx.x >> 5, lane_ = threadIdx.x & 31; \
      const int wm_ = (wid_ >> 2)*64, wn_ = (wid_ & 3)*32; \
      const int g_ = lane_ >> 2, t_ = lane_ & 3; \
      _Pragma("unroll") for (int mt = 0; mt < 4; mt++) \
      _Pragma("unroll") for (int nt = 0; nt < 4; nt++) \
      _Pragma("unroll") for (int hq = 0; hq < 2; hq++) { \
          int row = m0 + wm_ + mt*16 + g_ + 8*hq; \
          int col = n0 + wn_ + nt*8 + 2*t_; \
          float v0 = acc[mt][nt][2*hq], v1 = acc[mt][nt][2*hq+1];
#define EPI2_END } }

// ---------------- fp32 -> fp16 conversion --------------------------------------
__global__ void __launch_bounds__(256) k_cvt(const float* __restrict__ s,
                                             __half* __restrict__ d) {
    int i = (blockIdx.x*256 + threadIdx.x) * 4;
    float4 f = *(const float4*)(s + i);
    *(__half2*)(d + i)     = __floats2half2_rn(f.x, f.y);
    *(__half2*)(d + i + 2) = __floats2half2_rn(f.z, f.w);
}

// ---------------- EMA: 3-phase chunked linear scan -----------------------------
__device__ __forceinline__ void ema_params(int e, const float* delta, const float* alpha,
        float& q0, float& q1) {
    float p0 = sigf(delta[e*2+0]);
    float p1 = sigf(delta[e*2+1]);
    q0 = 1.f - p0*sigf(alpha[e*2+0]);
    q1 = 1.f - p1*sigf(alpha[e*2+1]);
}

__global__ void __launch_bounds__(256) k_ema_a(const float* __restrict__ x,
        const float* __restrict__ delta, const float* __restrict__ alpha)
{
    const int gt = blockIdx.x*256 + threadIdx.x;
    const int be = gt & (B_*E_-1);
    const int c  = gt >> 13;
    const int e  = be & (E_-1);
    float q0, q1; ema_params(e, delta, alpha, q0, q1);
    float h0 = 0.f, h1 = 0.f;
    const float* xp = x + (size_t)(c*CL_)*(B_*E_) + be;
    #pragma unroll 4
    for (int l = 0; l < CL_; l++) {
        float xv = xp[(size_t)l*(B_*E_)];
        h0 = q0*h0 + xv;
        h1 = q1*h1 + xv;
    }
    g_hend[(size_t)c*(B_*E_) + be]       = h0;
    g_hend[(size_t)(CH_+c)*(B_*E_) + be] = h1;
}

__global__ void __launch_bounds__(256) k_ema_b(const float* __restrict__ delta,
        const float* __restrict__ alpha)
{
    const int be = blockIdx.x*256 + threadIdx.x;
    const int e  = be & (E_-1);
    float q0, q1; ema_params(e, delta, alpha, q0, q1);
    float qp0 = q0, qp1 = q1;
    #pragma unroll
    for (int i = 0; i < 6; i++) { qp0 *= qp0; qp1 *= qp1; }   // q^64
    float c0 = 0.f, c1 = 0.f;
    for (int c = 0; c < CH_; c++) {
        g_cin[(size_t)c*(B_*E_) + be]       = c0;
        g_cin[(size_t)(CH_+c)*(B_*E_) + be] = c1;
        c0 = qp0*c0 + g_hend[(size_t)c*(B_*E_) + be];
        c1 = qp1*c1 + g_hend[(size_t)(CH_+c)*(B_*E_) + be];
    }
}

__global__ void __launch_bounds__(256) k_ema_c(const float* __restrict__ x,
        const float* __restrict__ delta, const float* __restrict__ alpha,
        const float* __restrict__ ebeta, const float* __restrict__ egam,
        const float* __restrict__ omega)
{
    const int gt = blockIdx.x*256 + threadIdx.x;
    const int be = gt & (B_*E_-1);
    const int c  = gt >> 13;
    const int e  = be & (E_-1);
    float p0 = sigf(delta[e*2+0]);
    float p1 = sigf(delta[e*2+1]);
    float q0 = 1.f - p0*sigf(alpha[e*2+0]);
    float q1 = 1.f - p1*sigf(alpha[e*2+1]);
    const float sc = 0.70710678118654752f;
    float c0 = p0*ebeta[e*2+0]*egam[e*2+0]*sc;
    float c1 = p1*ebeta[e*2+1]*egam[e*2+1]*sc;
    float om = omega[e];
    float h0 = g_cin[(size_t)c*(B_*E_) + be];
    float h1 = g_cin[(size_t)(CH_+c)*(B_*E_) + be];
    const size_t base = (size_t)(c*CL_)*(B_*E_) + be;
    #pragma unroll 4
    for (int l = 0; l < CL_; l++) {
        float xv = x[base + (size_t)l*(B_*E_)];
        h0 = q0*h0 + xv;
        h1 = q1*h1 + xv;
        float o = c0*h0 + c1*h1 + xv*om;
        g_emah[base + (size_t)l*(B_*E_)] = __float2half_rn(siluf(o));
    }
}

// ---------------- kernel 2: mx = ema @ Wm^T + bm (fp32 + half outputs) ----------
__global__ void __launch_bounds__(256, 2) k_mx(const float* __restrict__ bm)
{
    extern __shared__ StageH st_dyn[];
    float acc[4][4][4]; ZERO_ACC4(acc);
    const int m0 = blockIdx.y*128, n0 = blockIdx.x*128;
    gemm_nt_h(g_emah, E_, g_Wmh, E_, E_, m0, n0, st_dyn, acc);
    EPI2_BEGIN
        float o0 = v0 + bm[col], o1 = v1 + bm[col+1];
        *(float2*)&g_mx[(size_t)row*Z_ + col] = make_float2(o0, o1);
        *(__half2*)&g_mxh[(size_t)row*Z_ + col] = __floats2half2_rn(o0, o1);
    EPI2_END
}

// ---------------- kernel 3: z (fp32 FFMA for precision; tiny) -------------------
struct TilesF { float As[16][132]; float Bs[16][132]; };
__global__ void __launch_bounds__(256) k_z(const float* __restrict__ Wz,
        const float* __restrict__ bz, const float* __restrict__ gamma,
        const float* __restrict__ beta)
{
    __shared__ TilesF s;
    float acc[8][8];
    #pragma unroll
    for (int i=0;i<8;i++)
        #pragma unroll
        for (int j=0;j<8;j++) acc[i][j]=0.f;
    const int m0 = blockIdx.y*128;
    const int tid = threadIdx.x;
    const int tm = (tid >> 4) << 3, tn = (tid & 15) << 3;
    for (int k0 = 0; k0 < Z_; k0 += 16) {
        #pragma unroll
        for (int j = 0; j < 8; j++) {
            int i = tid + 256*j;
            int row = i >> 4, kk = i & 15;
            s.As[kk][row] = g_mx[(size_t)(m0+row)*Z_ + k0 + kk];
            s.Bs[kk][row] = Wz[(size_t)row*Z_ + k0 + kk];
        }
        __syncthreads();
        #pragma unroll
        for (int kk = 0; kk < 16; kk++) {
            float a[8], b[8];
            *(float4*)&a[0] = *(const float4*)&s.As[kk][tm];
            *(float4*)&a[4] = *(const float4*)&s.As[kk][tm+4];
            *(float4*)&b[0] = *(const float4*)&s.Bs[kk][tn];
            *(float4*)&b[4] = *(const float4*)&s.Bs[kk][tn+4];
            #pragma unroll
            for (int i = 0; i < 8; i++)
                #pragma unroll
                for (int j = 0; j < 8; j++)
                    acc[i][j] += a[i]*b[j];
        }
        __syncthreads();
    }
    #pragma unroll
    for (int i = 0; i < 8; i++)
        #pragma unroll
        for (int j = 0; j < 8; j++) {
            int m = m0+tm+i, n = tn+j;
            float zz = siluf(acc[i][j] + bz[n]);
            g_qrh[(size_t)m*Z_ + n] = __float2half_rn(zz*gamma[n]    + beta[n]);
            g_krh[(size_t)m*Z_ + n] = __float2half_rn(zz*gamma[Z_+n] + beta[Z_+n]);
        }
}

// ---------------- kernel 4: base = x @ Wp^T + bp -> u(fp32), r(half), v(half) ---
__global__ void __launch_bounds__(256, 2) k_base(const float* __restrict__ bp)
{
    extern __shared__ StageH st_dyn[];
    float acc[4][4][4]; ZERO_ACC4(acc);
    const int m0 = blockIdx.y*128, n0 = blockIdx.x*128;
    gemm_nt_h(g_xh, E_, g_Wph, E_, E_, m0, n0, st_dyn, acc);
    EPI2_BEGIN
        float t0 = v0 + bp[col], t1 = v1 + bp[col+1];
        if (col < E_) {
            *(float2*)&g_u[(size_t)row*E_ + col] = make_float2(sigf(t0), sigf(t1));
        } else {
            float s0 = siluf(t0), s1 = siluf(t1);
            int n2 = col - E_;
            if (n2 < H_) *(__half2*)&g_rh[(size_t)row*H_ + n2]      = __floats2half2_rn(s0, s1);
            else         *(__half2*)&g_vh[(size_t)row*H_ + (n2-H_)] = __floats2half2_rn(s0, s1);
        }
    EPI2_END
}

// ---------------- kernel 5: S = relu(q k^T / L + bias)^2, causal, half out ------
__global__ void __launch_bounds__(256, 2) k_S(const float* __restrict__ rpw)
{
    const int b  = blockIdx.z;
    const int m0 = blockIdx.y*128, n0 = blockIdx.x*128;
    if (n0 > m0) return;
    extern __shared__ StageH st_dyn[];
    float acc[4][4][4]; ZERO_ACC4(acc);
    gemm_nt_h(g_qrh + b*Z_, B_*Z_, g_krh + b*Z_, B_*Z_, Z_, m0, n0, st_dyn, acc);
    __half* Sb = g_Sh + (size_t)b*L_*L_;
    const float inv = 1.f / (float)L_;
    EPI2_BEGIN
        float a0 = v0*inv + rpw[(L_-1) + col   - row];
        float a1 = v1*inv + rpw[(L_-1) + col+1 - row];
        a0 = (col   <= row) ? fmaxf(a0, 0.f) : 0.f;
        a1 = (col+1 <= row) ? fmaxf(a1, 0.f) : 0.f;
        *(__half2*)&Sb[(size_t)row*L_ + col] = __floats2half2_rn(a0*a0, a1*a1);
    EPI2_END
}

// ---------------- kernel 6: hr = (S @ v) * r  (NN, v natural layout) ------------
__global__ void __launch_bounds__(256, 2) k_h()
{
    const int b  = blockIdx.z;
    const int m0 = blockIdx.y*128, n0 = blockIdx.x*128;
    extern __shared__ StageN st_dynN[];
    float acc[4][4][4]; ZERO_ACC4(acc);
    gemm_nn_h(g_Sh + (size_t)b*L_*L_, L_,
              g_vh + (size_t)b*H_ + n0, (size_t)B_*H_,
              m0 + 128, m0, st_dynN, acc);
    EPI2_BEGIN
        size_t idx = (size_t)(row*B_ + b)*H_ + col;
        __half2 rr = *(const __half2*)&g_rh[idx];
        float2 rf = __half22float2(rr);
        *(__half2*)&g_hrh[idx] = __floats2half2_rn(v0*rf.x, v1*rf.y);
    EPI2_END
}

// ---------------- kernel 7: out = x + u*(tanh(hr Whw^T + mx Whu^T + b) - x) -----
__global__ void __launch_bounds__(256, 2) k_final(const float* __restrict__ x,
        const float* __restrict__ bhw, const float* __restrict__ bhu,
        float* __restrict__ out)
{
    extern __shared__ StageH st_dyn[];
    float acc[4][4][4]; ZERO_ACC4(acc);
    const int m0 = blockIdx.y*128, n0 = blockIdx.x*128;
    gemm_nt_h(g_hrh, H_, g_Whwh, H_, H_, m0, n0, st_dyn, acc);
    gemm_nt_h(g_mxh, Z_, g_Whuh, Z_, Z_, m0, n0, st_dyn, acc);
    EPI2_BEGIN
        float t0 = v0 + bhw[col]   + bhu[col];
        float t1 = v1 + bhw[col+1] + bhu[col+1];
        size_t idx = (size_t)row*E_ + col;
        float2 xv = *(const float2*)&x[idx];
        float2 uu = *(const float2*)&g_u[idx];
        float2 o = make_float2(xv.x + uu.x*(tanhf(t0) - xv.x),
                               xv.y + uu.y*(tanhf(t1) - xv.y));
        *(float2*)&out[idx] = o;
    EPI2_END
}

// -----------------------------------------------------------------------------
extern "C" void kernel_launch(void* const* d_in, const int* in_sizes, int n_in,
                              void* d_out, int out_size)
{
    const float* x     = (const float*)d_in[0];
    const float* delta = (const float*)d_in[2];
    const float* alpha = (const float*)d_in[3];
    const float* ebeta = (const float*)d_in[4];
    const float* egam  = (const float*)d_in[5];
    const float* omega = (const float*)d_in[6];
    const float* Wm    = (const float*)d_in[7];
    const float* bm    = (const float*)d_in[8];
    const float* Wz    = (const float*)d_in[9];
    const float* bz    = (const float*)d_in[10];
    const float* Wp    = (const float*)d_in[11];
    const float* bp    = (const float*)d_in[12];
    const float* Whw   = (const float*)d_in[13];
    const float* bhw   = (const float*)d_in[14];
    const float* Whu   = (const float*)d_in[15];
    const float* bhu   = (const float*)d_in[16];
    const float* gamma = (const float*)d_in[17];
    const float* beta  = (const float*)d_in[18];
    const float* rpw   = (const float*)d_in[19];
    float* out = (float*)d_out;

    __half *xh_p, *Wph_p, *Wmh_p, *Whwh_p, *Whuh_p;
    cudaGetSymbolAddress((void**)&xh_p,   g_xh);
    cudaGetSymbolAddress((void**)&Wph_p,  g_Wph);
    cudaGetSymbolAddress((void**)&Wmh_p,  g_Wmh);
    cudaGetSymbolAddress((void**)&Whwh_p, g_Whwh);
    cudaGetSymbolAddress((void**)&Whuh_p, g_Whuh);

    cudaFuncSetAttribute(k_mx,    cudaFuncAttributeMaxDynamicSharedMemorySize, SMEM_BYTES);
    cudaFuncSetAttribute(k_base,  cudaFuncAttributeMaxDynamicSharedMemorySize, SMEM_BYTES);
    cudaFuncSetAttribute(k_S,     cudaFuncAttributeMaxDynamicSharedMemorySize, SMEM_BYTES);
    cudaFuncSetAttribute(k_h,     cudaFuncAttributeMaxDynamicSharedMemorySize, SMEMN_BYTES);
    cudaFuncSetAttribute(k_final, cudaFuncAttributeMaxDynamicSharedMemorySize, SMEM_BYTES);

    static cudaStream_t s2 = nullptr;
    static cudaEvent_t e_fork = nullptr, e_join = nullptr;
    if (s2 == nullptr) {
        cudaStreamCreateWithFlags(&s2, cudaStreamNonBlocking);
        cudaEventCreateWithFlags(&e_fork, cudaEventDisableTiming);
        cudaEventCreateWithFlags(&e_join, cudaEventDisableTiming);
    }

    cudaEventRecord(e_fork, 0);
    cudaStreamWaitEvent(s2, e_fork, 0);

    // ---- branch A on s2: cvt(x, Wp) -> k_base (no vT pass needed) ----
    k_cvt <<<MB_*E_/1024, 256, 0, s2>>>(x,  xh_p);
    k_cvt <<<(E_+2*H_)*E_/1024, 256, 0, s2>>>(Wp, Wph_p);
    k_base<<<dim3(40, 128), 256, SMEM_BYTES, s2>>>(bp);
    cudaEventRecord(e_join, s2);

    // ---- branch B on default stream ----
    k_cvt  <<<Z_*E_/1024, 256>>>(Wm,  Wmh_p);
    k_cvt  <<<E_*H_/1024, 256>>>(Whw, Whwh_p);
    k_cvt  <<<E_*Z_/1024, 256>>>(Whu, Whuh_p);
    k_ema_a<<<CH_*B_*E_/256, 256>>>(x, delta, alpha);
    k_ema_b<<<B_*E_/256, 256>>>(delta, alpha);
    k_ema_c<<<CH_*B_*E_/256, 256>>>(x, delta, alpha, ebeta, egam, omega);
    k_mx   <<<dim3(1, 128),    256, SMEM_BYTES>>>(bm);
    k_z    <<<dim3(1, 128),    256>>>(Wz, bz, gamma, beta);
    k_S    <<<dim3(16, 16, 8), 256, SMEM_BYTES>>>(rpw);

    // ---- join: k_h needs S (B) + v, r (A) ----
    cudaStreamWaitEvent(0, e_join, 0);
    k_h    <<<dim3(16, 16, 8), 256, SMEMN_BYTES>>>();
    k_final<<<dim3(8, 128),    256, SMEM_BYTES>>>(x, bhw, bhu, out);
}